// round 4
// baseline (speedup 1.0000x reference)
#include <cuda_runtime.h>
#include <cuda_bf16.h>
#include <math_constants.h>
#include <cstdint>

#define N_USERS   100000
#define M_ITEMS   50000
#define N_NODES   (N_USERS + M_ITEMS)
#define LATENT    64
#define N_CATS    1000
#define N_LAYERS  3
#define TIME_BINS 24
#define NNZ       4800000
#define BATCH     1024
#define ALPHA     0.5f
#define M_PAD     50048          // 391 * 128

#define NODEF (N_NODES * LATENT)   // 9.6M floats
#define SCAN_CHUNK 1024
#define NBLK ((N_NODES + SCAN_CHUNK - 1) / SCAN_CHUNK)   // 147

// ---------------- device scratch (static: no allocs allowed) ----------------
__device__ float g_e0[NODEF];
__device__ float g_e1[NODEF];
__device__ float g_acc[NODEF];
__device__ __align__(16) __nv_bfloat16 g_Qh[BATCH * 128];
__device__ __align__(16) __nv_bfloat16 g_Ql[BATCH * 128];
__device__ __align__(16) __nv_bfloat16 g_Ih[M_PAD * 128];
__device__ __align__(16) __nv_bfloat16 g_Il[M_PAD * 128];
__device__ int2  g_edge[NNZ];          // (val bits, col) reordered by row
__device__ int   g_cnt[N_NODES];
__device__ int   g_rowstart[N_NODES];
__device__ int   g_cursor[N_NODES];
__device__ int   g_blocksums[NBLK];

// ---------------- helpers ----------------
__device__ __forceinline__ uint32_t smem_to_u32(const void* p) {
    uint32_t a;
    asm("{ .reg .u64 t; cvta.to.shared.u64 t, %1; cvt.u32.u64 %0, t; }" : "=r"(a) : "l"(p));
    return a;
}
__device__ __forceinline__ void ldsm_x4(uint32_t* d, uint32_t addr) {
    asm volatile("ldmatrix.sync.aligned.m8n8.x4.shared.b16 {%0,%1,%2,%3}, [%4];"
                 : "=r"(d[0]), "=r"(d[1]), "=r"(d[2]), "=r"(d[3]) : "r"(addr));
}
__device__ __forceinline__ void mma_bf16(float* c, const uint32_t* a, const uint32_t* b) {
    asm volatile("mma.sync.aligned.m16n8k16.row.col.f32.bf16.bf16.f32 "
                 "{%0,%1,%2,%3}, {%4,%5,%6,%7}, {%8,%9}, {%0,%1,%2,%3};"
                 : "+f"(c[0]), "+f"(c[1]), "+f"(c[2]), "+f"(c[3])
                 : "r"(a[0]), "r"(a[1]), "r"(a[2]), "r"(a[3]), "r"(b[0]), "r"(b[1]));
}

// ---------------- init: e0 = acc = concat(user_emb, item_emb) ----------------
__global__ void k_init(const float* __restrict__ ue, const float* __restrict__ ie,
                       float* __restrict__ e0, float* __restrict__ acc) {
    int i = blockIdx.x * blockDim.x + threadIdx.x;       // float4 index
    const int total = N_NODES * (LATENT / 4);
    const int usplit = N_USERS * (LATENT / 4);
    if (i < total) {
        float4 v = (i < usplit) ? ((const float4*)ue)[i]
                                : ((const float4*)ie)[i - usplit];
        ((float4*)e0)[i] = v;
        ((float4*)acc)[i] = v;
    }
}

// ---------------- CSR build: count ----------------
__global__ void k_count(const int* __restrict__ rows, int* __restrict__ cnt) {
    int e = blockIdx.x * blockDim.x + threadIdx.x;
    if (e < NNZ) atomicAdd(&cnt[rows[e]], 1);
}

// ---------------- CSR build: per-chunk exclusive scan ----------------
__global__ __launch_bounds__(256) void k_scan_blocks(const int* __restrict__ cnt,
                                                     int* __restrict__ rowstart,
                                                     int* __restrict__ blocksums) {
    __shared__ int wsum[8];
    __shared__ int woff[8];
    int tid  = threadIdx.x;
    int lane = tid & 31;
    int warp = tid >> 5;
    int base = blockIdx.x * SCAN_CHUNK + tid * 4;

    int c0 = 0, c1 = 0, c2 = 0, c3 = 0;
    if (base + 3 < N_NODES) {
        int4 c = *(const int4*)(cnt + base);
        c0 = c.x; c1 = c.y; c2 = c.z; c3 = c.w;
    } else {
        if (base + 0 < N_NODES) c0 = cnt[base + 0];
        if (base + 1 < N_NODES) c1 = cnt[base + 1];
        if (base + 2 < N_NODES) c2 = cnt[base + 2];
        if (base + 3 < N_NODES) c3 = cnt[base + 3];
    }
    int tsum = c0 + c1 + c2 + c3;

    int inc = tsum;
    #pragma unroll
    for (int off = 1; off < 32; off <<= 1) {
        int n = __shfl_up_sync(0xffffffffu, inc, off);
        if (lane >= off) inc += n;
    }
    if (lane == 31) wsum[warp] = inc;
    __syncthreads();
    if (tid == 0) {
        int r = 0;
        #pragma unroll
        for (int i = 0; i < 8; i++) { woff[i] = r; r += wsum[i]; }
        blocksums[blockIdx.x] = r;
    }
    __syncthreads();

    int excl = woff[warp] + (inc - tsum);
    if (base + 0 < N_NODES) rowstart[base + 0] = excl;
    if (base + 1 < N_NODES) rowstart[base + 1] = excl + c0;
    if (base + 2 < N_NODES) rowstart[base + 2] = excl + c0 + c1;
    if (base + 3 < N_NODES) rowstart[base + 3] = excl + c0 + c1 + c2;
}

__global__ void k_scan_sums(int* __restrict__ blocksums) {
    if (threadIdx.x == 0 && blockIdx.x == 0) {
        int r = 0;
        for (int i = 0; i < NBLK; i++) { int v = blocksums[i]; blocksums[i] = r; r += v; }
    }
}

__global__ void k_add_offsets(int* __restrict__ rowstart,
                              const int* __restrict__ blocksums,
                              int* __restrict__ cursor) {
    int i = blockIdx.x * blockDim.x + threadIdx.x;
    if (i < N_NODES) {
        int r = rowstart[i] + blocksums[i / SCAN_CHUNK];
        rowstart[i] = r;
        cursor[i]   = r;
    }
}

__global__ void k_fill(const float* __restrict__ vals,
                       const int*   __restrict__ rows,
                       const int*   __restrict__ cols,
                       int* __restrict__ cursor,
                       int2* __restrict__ edge) {
    int e = blockIdx.x * blockDim.x + threadIdx.x;
    if (e < NNZ) {
        int r = rows[e];
        int pos = atomicAdd(&cursor[r], 1);
        edge[pos] = make_int2(__float_as_int(vals[e]), cols[e]);
    }
}

// ---------------- layer: atomic-free segment gather, fused acc += e ----------------
__global__ __launch_bounds__(256) void k_gather(const int2* __restrict__ edge,
                                                const int*  __restrict__ rowstart,
                                                const int*  __restrict__ cnt,
                                                const float* __restrict__ esrc,
                                                float*       __restrict__ edst,
                                                float*       __restrict__ acc,
                                                int writeE) {
    int g   = blockIdx.x * blockDim.x + threadIdx.x;
    int row = g >> 4;
    int t   = g & 15;
    if (row >= N_NODES) return;
    unsigned hmask = 0xFFFFu << (threadIdx.x & 16);   // own half-warp

    int start = rowstart[row];
    int deg   = cnt[row];
    float4 s = make_float4(0.f, 0.f, 0.f, 0.f);

    for (int base = 0; base < deg; base += 16) {
        int rem = deg - base;
        int2 ev = (t < rem) ? __ldg(&edge[start + base + t]) : make_int2(0, 0);
        int lim = rem < 16 ? rem : 16;
        #pragma unroll 4
        for (int k = 0; k < lim; k++) {
            float v = __int_as_float(__shfl_sync(hmask, ev.x, k, 16));
            int   c = __shfl_sync(hmask, ev.y, k, 16);
            float4 m = __ldg(&((const float4*)esrc)[c * (LATENT / 4) + t]);
            s.x += v * m.x; s.y += v * m.y; s.z += v * m.z; s.w += v * m.w;
        }
    }

    int idx = row * (LATENT / 4) + t;
    if (writeE) ((float4*)edst)[idx] = s;
    float4 a = ((float4*)acc)[idx];
    a.x += s.x; a.y += s.y; a.z += s.z; a.w += s.w;
    ((float4*)acc)[idx] = a;
}

// ---------------- hi/lo bf16 split helper ----------------
__device__ __forceinline__ void split_bf16(float x, __nv_bfloat16& hi, __nv_bfloat16& lo) {
    hi = __float2bfloat16(x);
    lo = __float2bfloat16(x - __bfloat162float(hi));
}

// ---------------- clock: Q[b] = [0.25*acc[user] | alpha*v_clock] as bf16 hi/lo ----------------
__global__ void k_clock(const float* __restrict__ acc,
                        const float* __restrict__ cat_emb,
                        const int*   __restrict__ uh3,
                        const int*   __restrict__ users,
                        const float* __restrict__ thetas,
                        __nv_bfloat16* __restrict__ Qh,
                        __nv_bfloat16* __restrict__ Ql) {
    int b = blockIdx.x;
    int d = threadIdx.x;       // 64 threads
    __shared__ float w[TIME_BINS];
    __shared__ float sinv;
    int u = users[b];
    if (d < TIME_BINS) {
        float cur = thetas[b] * (float)(TIME_BINS / (2.0 * CUDART_PI));
        float diff = fabsf(cur - (float)d);
        float delta = fminf(diff, (float)TIME_BINS - diff);
        w[d] = __expf(-0.5f * delta * delta);
    }
    __syncthreads();
    if (d == 0) {
        float s = 0.f;
        #pragma unroll
        for (int h = 0; h < TIME_BINS; h++) s += w[h];
        sinv = 1.0f / (s + 1e-8f);
    }
    __syncthreads();
    float inv3 = sinv * (1.0f / 3.0f);
    float v = 0.f;
    const int* base = &uh3[u * TIME_BINS * 3];
    #pragma unroll 4
    for (int h = 0; h < TIME_BINS; h++) {
        int c0 = base[h * 3 + 0], c1 = base[h * 3 + 1], c2 = base[h * 3 + 2];
        float e = cat_emb[c0 * 64 + d] + cat_emb[c1 * 64 + d] + cat_emb[c2 * 64 + d];
        v += w[h] * e;
    }
    v *= inv3;
    float q0 = 0.25f * acc[u * LATENT + d];
    float q1 = ALPHA * v;
    __nv_bfloat16 h0, l0, h1, l1;
    split_bf16(q0, h0, l0);
    split_bf16(q1, h1, l1);
    Qh[b * 128 + d]      = h0;  Ql[b * 128 + d]      = l0;
    Qh[b * 128 + 64 + d] = h1;  Ql[b * 128 + 64 + d] = l1;
}

// ---------------- items: IT[m] = [0.25*acc[N_USERS+m] | cat_emb[item_cat[m]]] bf16 hi/lo ----------------
__global__ void k_items(const float* __restrict__ acc,
                        const float* __restrict__ cat_emb,
                        const int*   __restrict__ item_cat,
                        __nv_bfloat16* __restrict__ Ih,
                        __nv_bfloat16* __restrict__ Il) {
    int g = blockIdx.x * blockDim.x + threadIdx.x;
    int m = g >> 6;
    int d = g & 63;
    if (m >= M_PAD) return;
    if (m < M_ITEMS) {
        float a = 0.25f * acc[(N_USERS + m) * LATENT + d];
        float c = cat_emb[item_cat[m] * 64 + d];
        __nv_bfloat16 h0, l0, h1, l1;
        split_bf16(a, h0, l0);
        split_bf16(c, h1, l1);
        Ih[m * 128 + d]      = h0;  Il[m * 128 + d]      = l0;
        Ih[m * 128 + 64 + d] = h1;  Il[m * 128 + 64 + d] = l1;
    } else {
        __nv_bfloat16 z = __float2bfloat16(0.f);
        Ih[m * 128 + d] = z;       Il[m * 128 + d] = z;
        Ih[m * 128 + 64 + d] = z;  Il[m * 128 + 64 + d] = z;
    }
}

// ---------------- mma.sync GEMM: C[1024,50000] = Q @ IT^T, 3xBF16 split ----------------
// SMEM: 4 tiles of 128x128 bf16 (256B/row, 16 chunks of 16B, XOR-8 swizzled)
#define SM_AH 0
#define SM_AL 32768
#define SM_BH 65536
#define SM_BL 98304
#define SM_TOTAL 131072

__global__ __launch_bounds__(256, 1) void k_gemm_mma(const __nv_bfloat16* __restrict__ Qh,
                                                     const __nv_bfloat16* __restrict__ Ql,
                                                     const __nv_bfloat16* __restrict__ Ih,
                                                     const __nv_bfloat16* __restrict__ Il,
                                                     float* __restrict__ C) {
    extern __shared__ __align__(1024) char smem[];
    uint32_t sbase = smem_to_u32(smem);
    const int tid  = threadIdx.x;
    const int wid  = tid >> 5;
    const int lane = tid & 31;
    const int n0 = blockIdx.x * 128;   // item tile
    const int m0 = blockIdx.y * 128;   // batch tile

    // ---- load the 4 tiles into swizzled SMEM ----
    {
        const int r    = tid >> 1;      // row 0..127
        const int half = tid & 1;       // chunks 0-7 / 8-15
        const __nv_bfloat16* srcs[4] = {
            Qh + (size_t)(m0 + r) * 128 + half * 64,
            Ql + (size_t)(m0 + r) * 128 + half * 64,
            Ih + (size_t)(n0 + r) * 128 + half * 64,
            Il + (size_t)(n0 + r) * 128 + half * 64 };
        const int dsts[4] = { SM_AH, SM_AL, SM_BH, SM_BL };
        const int rs = r & 7;
        #pragma unroll
        for (int t = 0; t < 4; t++) {
            const uint4* s = (const uint4*)srcs[t];
            char* drow = smem + dsts[t] + r * 256;
            #pragma unroll
            for (int i = 0; i < 8; i++) {
                int c = half * 8 + i;
                *(uint4*)(drow + ((c ^ rs) << 4)) = __ldg(&s[i]);
            }
        }
    }
    __syncthreads();

    const int warp_m = wid & 3;        // 4 warps along M (32 rows each)
    const int warp_n = wid >> 2;       // 2 warps along N (64 cols each)

    float acc[2][8][4];
    #pragma unroll
    for (int i = 0; i < 2; i++)
        #pragma unroll
        for (int j = 0; j < 8; j++)
            #pragma unroll
            for (int q = 0; q < 4; q++) acc[i][j][q] = 0.f;

    // ldmatrix lane address components
    const int a_row = warp_m * 32 + (lane & 7) + ((lane >> 3) & 1) * 8;   // + i*16
    const int a_ch  = (lane >> 4) & 1;
    const int b_row = warp_n * 64 + (lane & 7) + ((lane >> 4) & 1) * 8;   // + jj*16
    const int b_ch  = (lane >> 3) & 1;

    #pragma unroll
    for (int p = 0; p < 3; p++) {
        uint32_t Abase = sbase + (p == 2 ? SM_AL : SM_AH);
        uint32_t Bbase = sbase + (p == 1 ? SM_BL : SM_BH);
        #pragma unroll
        for (int ks = 0; ks < 8; ks++) {
            uint32_t af[2][4];
            uint32_t bf[8][2];
            #pragma unroll
            for (int i = 0; i < 2; i++) {
                int r = a_row + i * 16;
                int c = ks * 2 + a_ch;
                ldsm_x4(af[i], Abase + r * 256 + (((c ^ (r & 7))) << 4));
            }
            #pragma unroll
            for (int jj = 0; jj < 4; jj++) {
                int r = b_row + jj * 16;
                int c = ks * 2 + b_ch;
                uint32_t d[4];
                ldsm_x4(d, Bbase + r * 256 + (((c ^ (r & 7))) << 4));
                bf[2 * jj][0]     = d[0];
                bf[2 * jj][1]     = d[1];
                bf[2 * jj + 1][0] = d[2];
                bf[2 * jj + 1][1] = d[3];
            }
            #pragma unroll
            for (int i = 0; i < 2; i++)
                #pragma unroll
                for (int j = 0; j < 8; j++)
                    mma_bf16(acc[i][j], af[i], bf[j]);
        }
    }

    // ---- epilogue: write fp32 fragments ----
    const int gm = lane >> 2;
    const int gn = (lane & 3) * 2;
    #pragma unroll
    for (int i = 0; i < 2; i++) {
        int row = m0 + warp_m * 32 + i * 16 + gm;
        float* c0 = C + (size_t)row * M_ITEMS;
        float* c1 = C + (size_t)(row + 8) * M_ITEMS;
        #pragma unroll
        for (int j = 0; j < 8; j++) {
            int col = n0 + warp_n * 64 + j * 8 + gn;
            if (col < M_ITEMS) {
                *(float2*)(c0 + col) = make_float2(acc[i][j][0], acc[i][j][1]);
                *(float2*)(c1 + col) = make_float2(acc[i][j][2], acc[i][j][3]);
            }
        }
    }
}

// ---------------- launch ----------------
extern "C" void kernel_launch(void* const* d_in, const int* in_sizes, int n_in,
                              void* d_out, int out_size) {
    const float* user_emb  = (const float*)d_in[0];
    const float* item_emb  = (const float*)d_in[1];
    const float* cat_emb   = (const float*)d_in[2];
    const float* graph_vals= (const float*)d_in[3];
    const int*   graph_rows= (const int*)  d_in[4];
    const int*   graph_cols= (const int*)  d_in[5];
    const int*   uh3       = (const int*)  d_in[6];
    const int*   item_cat  = (const int*)  d_in[7];
    const int*   users     = (const int*)  d_in[8];
    const float* thetas    = (const float*)d_in[9];
    float* out = (float*)d_out;

    float *d_e0, *d_e1, *d_acc;
    __nv_bfloat16 *d_Qh, *d_Ql, *d_Ih, *d_Il;
    int2* d_edge; int *d_cnt, *d_rowstart, *d_cursor, *d_blocksums;
    cudaGetSymbolAddress((void**)&d_e0,       g_e0);
    cudaGetSymbolAddress((void**)&d_e1,       g_e1);
    cudaGetSymbolAddress((void**)&d_acc,      g_acc);
    cudaGetSymbolAddress((void**)&d_Qh,       g_Qh);
    cudaGetSymbolAddress((void**)&d_Ql,       g_Ql);
    cudaGetSymbolAddress((void**)&d_Ih,       g_Ih);
    cudaGetSymbolAddress((void**)&d_Il,       g_Il);
    cudaGetSymbolAddress((void**)&d_edge,     g_edge);
    cudaGetSymbolAddress((void**)&d_cnt,      g_cnt);
    cudaGetSymbolAddress((void**)&d_rowstart, g_rowstart);
    cudaGetSymbolAddress((void**)&d_cursor,   g_cursor);
    cudaGetSymbolAddress((void**)&d_blocksums,g_blocksums);

    cudaFuncSetAttribute(k_gemm_mma, cudaFuncAttributeMaxDynamicSharedMemorySize, SM_TOTAL);

    // ---- CSR build (once; reused by all 3 layers) ----
    cudaMemsetAsync(d_cnt, 0, (size_t)N_NODES * sizeof(int), 0);
    k_count<<<(NNZ + 255) / 256, 256>>>(graph_rows, d_cnt);
    k_scan_blocks<<<NBLK, 256>>>(d_cnt, d_rowstart, d_blocksums);
    k_scan_sums<<<1, 32>>>(d_blocksums);
    k_add_offsets<<<(N_NODES + 255) / 256, 256>>>(d_rowstart, d_blocksums, d_cursor);
    k_fill<<<(NNZ + 255) / 256, 256>>>(graph_vals, graph_rows, graph_cols, d_cursor, d_edge);

    // ---- init embeddings ----
    {
        int total = N_NODES * (LATENT / 4);
        k_init<<<(total + 255) / 256, 256>>>(user_emb, item_emb, d_e0, d_acc);
    }

    // ---- 3 LightGCN layers ----
    {
        int th = N_NODES * 16;
        int blocks = (th + 255) / 256;
        k_gather<<<blocks, 256>>>(d_edge, d_rowstart, d_cnt, d_e0, d_e1, d_acc, 1);
        k_gather<<<blocks, 256>>>(d_edge, d_rowstart, d_cnt, d_e1, d_e0, d_acc, 1);
        k_gather<<<blocks, 256>>>(d_edge, d_rowstart, d_cnt, d_e0, d_e1, d_acc, 0);
    }

    // ---- Q side (bf16 hi/lo) ----
    k_clock<<<BATCH, 64>>>(d_acc, cat_emb, uh3, users, thetas, d_Qh, d_Ql);

    // ---- item side (bf16 hi/lo) ----
    {
        int total = M_PAD * 64;
        k_items<<<(total + 255) / 256, 256>>>(d_acc, cat_emb, item_cat, d_Ih, d_Il);
    }

    // ---- tensor-core GEMM ----
    {
        dim3 grid(M_PAD / 128, BATCH / 128);
        k_gemm_mma<<<grid, 256, SM_TOTAL>>>(d_Qh, d_Ql, d_Ih, d_Il, out);
    }
}

// round 5
// speedup vs baseline: 1.2488x; 1.2488x over previous
#include <cuda_runtime.h>
#include <cuda_bf16.h>
#include <math_constants.h>
#include <cstdint>

#define N_USERS   100000
#define M_ITEMS   50000
#define N_NODES   (N_USERS + M_ITEMS)
#define LATENT    64
#define N_CATS    1000
#define N_LAYERS  3
#define TIME_BINS 24
#define NNZ       4800000
#define BATCH     1024
#define ALPHA     0.5f
#define M_PAD     50048          // 391 * 128

#define NODEF (N_NODES * LATENT)   // 9.6M floats
#define SCAN_CHUNK 1024
#define NBLK ((N_NODES + SCAN_CHUNK - 1) / SCAN_CHUNK)   // 147

typedef unsigned long long ull;

// ---------------- device scratch (static: no allocs allowed) ----------------
__device__ float g_e0[NODEF];
__device__ float g_e1[NODEF];
__device__ float g_acc[NODEF];
__device__ float g_Q[BATCH * 128];
__device__ float g_item[M_PAD * 128];
__device__ int2  g_edge[NNZ];          // (val bits, col) reordered by row
__device__ int   g_cnt[N_NODES];
__device__ int   g_rowstart[N_NODES];
__device__ int   g_cursor[N_NODES];
__device__ int   g_blocksums[NBLK];
__device__ unsigned char g_need[N_USERS];

// ---------------- f32x2 helpers ----------------
__device__ __forceinline__ ull pack2(float x, float y) {
    ull p;
    asm("mov.b64 %0, {%1, %2};" : "=l"(p) : "f"(x), "f"(y));
    return p;
}
__device__ __forceinline__ ull dup2(float x) {
    ull p;
    asm("mov.b64 %0, {%1, %1};" : "=l"(p) : "f"(x));
    return p;
}
__device__ __forceinline__ void fma2(ull& c, ull a, ull b) {
    asm("fma.rn.f32x2 %0, %1, %2, %0;" : "+l"(c) : "l"(a), "l"(b));
}
__device__ __forceinline__ float2 unpack2(ull p) {
    float2 v;
    asm("mov.b64 {%0, %1}, %2;" : "=f"(v.x), "=f"(v.y) : "l"(p));
    return v;
}

// ---------------- init: e0 = acc = concat(user_emb, item_emb) ----------------
__global__ void k_init(const float* __restrict__ ue, const float* __restrict__ ie,
                       float* __restrict__ e0, float* __restrict__ acc) {
    int i = blockIdx.x * blockDim.x + threadIdx.x;       // float4 index
    const int total = N_NODES * (LATENT / 4);
    const int usplit = N_USERS * (LATENT / 4);
    if (i < total) {
        float4 v = (i < usplit) ? ((const float4*)ue)[i]
                                : ((const float4*)ie)[i - usplit];
        ((float4*)e0)[i] = v;
        ((float4*)acc)[i] = v;
    }
}

// ---------------- CSR build: count ----------------
__global__ void k_count(const int* __restrict__ rows, int* __restrict__ cnt) {
    int e = blockIdx.x * blockDim.x + threadIdx.x;
    if (e < NNZ) atomicAdd(&cnt[rows[e]], 1);
}

// ---------------- CSR build: per-chunk exclusive scan ----------------
__global__ __launch_bounds__(256) void k_scan_blocks(const int* __restrict__ cnt,
                                                     int* __restrict__ rowstart,
                                                     int* __restrict__ blocksums) {
    __shared__ int wsum[8];
    __shared__ int woff[8];
    int tid  = threadIdx.x;
    int lane = tid & 31;
    int warp = tid >> 5;
    int base = blockIdx.x * SCAN_CHUNK + tid * 4;

    int c0 = 0, c1 = 0, c2 = 0, c3 = 0;
    if (base + 3 < N_NODES) {
        int4 c = *(const int4*)(cnt + base);
        c0 = c.x; c1 = c.y; c2 = c.z; c3 = c.w;
    } else {
        if (base + 0 < N_NODES) c0 = cnt[base + 0];
        if (base + 1 < N_NODES) c1 = cnt[base + 1];
        if (base + 2 < N_NODES) c2 = cnt[base + 2];
        if (base + 3 < N_NODES) c3 = cnt[base + 3];
    }
    int tsum = c0 + c1 + c2 + c3;

    int inc = tsum;
    #pragma unroll
    for (int off = 1; off < 32; off <<= 1) {
        int n = __shfl_up_sync(0xffffffffu, inc, off);
        if (lane >= off) inc += n;
    }
    if (lane == 31) wsum[warp] = inc;
    __syncthreads();
    if (tid == 0) {
        int r = 0;
        #pragma unroll
        for (int i = 0; i < 8; i++) { woff[i] = r; r += wsum[i]; }
        blocksums[blockIdx.x] = r;
    }
    __syncthreads();

    int excl = woff[warp] + (inc - tsum);
    if (base + 0 < N_NODES) rowstart[base + 0] = excl;
    if (base + 1 < N_NODES) rowstart[base + 1] = excl + c0;
    if (base + 2 < N_NODES) rowstart[base + 2] = excl + c0 + c1;
    if (base + 3 < N_NODES) rowstart[base + 3] = excl + c0 + c1 + c2;
}

__global__ void k_scan_sums(int* __restrict__ blocksums) {
    if (threadIdx.x == 0 && blockIdx.x == 0) {
        int r = 0;
        for (int i = 0; i < NBLK; i++) { int v = blocksums[i]; blocksums[i] = r; r += v; }
    }
}

__global__ void k_add_offsets(int* __restrict__ rowstart,
                              const int* __restrict__ blocksums,
                              int* __restrict__ cursor) {
    int i = blockIdx.x * blockDim.x + threadIdx.x;
    if (i < N_NODES) {
        int r = rowstart[i] + blocksums[i / SCAN_CHUNK];
        rowstart[i] = r;
        cursor[i]   = r;
    }
}

__global__ void k_fill(const float* __restrict__ vals,
                       const int*   __restrict__ rows,
                       const int*   __restrict__ cols,
                       int* __restrict__ cursor,
                       int2* __restrict__ edge) {
    int e = blockIdx.x * blockDim.x + threadIdx.x;
    if (e < NNZ) {
        int r = rows[e];
        int pos = atomicAdd(&cursor[r], 1);
        edge[pos] = make_int2(__float_as_int(vals[e]), cols[e]);
    }
}

// ---------------- needed-row flags for layer 3 ----------------
__global__ void k_setflags(const int* __restrict__ users, unsigned char* __restrict__ need) {
    int i = blockIdx.x * blockDim.x + threadIdx.x;
    if (i < BATCH) need[users[i]] = 1;
}

// ---------------- layer: atomic-free segment gather, fused acc += e ----------------
// selective != 0: skip user rows not flagged in `need` (their acc is never read)
__global__ __launch_bounds__(256) void k_gather(const int2* __restrict__ edge,
                                                const int*  __restrict__ rowstart,
                                                const int*  __restrict__ cnt,
                                                const float* __restrict__ esrc,
                                                float*       __restrict__ edst,
                                                float*       __restrict__ acc,
                                                const unsigned char* __restrict__ need,
                                                int writeE, int selective) {
    int g   = blockIdx.x * blockDim.x + threadIdx.x;
    int row = g >> 4;
    int t   = g & 15;
    if (row >= N_NODES) return;
    if (selective && row < N_USERS && !need[row]) return;
    unsigned hmask = 0xFFFFu << (threadIdx.x & 16);   // own half-warp

    int start = rowstart[row];
    int deg   = cnt[row];
    float4 s = make_float4(0.f, 0.f, 0.f, 0.f);

    for (int base = 0; base < deg; base += 16) {
        int rem = deg - base;
        int2 ev = (t < rem) ? __ldg(&edge[start + base + t]) : make_int2(0, 0);
        int lim = rem < 16 ? rem : 16;
        #pragma unroll 4
        for (int k = 0; k < lim; k++) {
            float v = __int_as_float(__shfl_sync(hmask, ev.x, k, 16));
            int   c = __shfl_sync(hmask, ev.y, k, 16);
            float4 m = __ldg(&((const float4*)esrc)[c * (LATENT / 4) + t]);
            s.x += v * m.x; s.y += v * m.y; s.z += v * m.z; s.w += v * m.w;
        }
    }

    int idx = row * (LATENT / 4) + t;
    if (writeE) ((float4*)edst)[idx] = s;
    float4 a = ((float4*)acc)[idx];
    a.x += s.x; a.y += s.y; a.z += s.z; a.w += s.w;
    ((float4*)acc)[idx] = a;
}

// ---------------- clock: build Q[b] = [0.25*acc[user] | alpha * v_clock] ----------------
__global__ void k_clock(const float* __restrict__ acc,
                        const float* __restrict__ cat_emb,
                        const int*   __restrict__ uh3,
                        const int*   __restrict__ users,
                        const float* __restrict__ thetas,
                        float*       __restrict__ Q) {
    int b = blockIdx.x;
    int d = threadIdx.x;       // 64 threads
    __shared__ float w[TIME_BINS];
    __shared__ float sinv;
    int u = users[b];
    if (d < TIME_BINS) {
        float cur = thetas[b] * (float)(TIME_BINS / (2.0 * CUDART_PI));
        float diff = fabsf(cur - (float)d);
        float delta = fminf(diff, (float)TIME_BINS - diff);
        w[d] = __expf(-0.5f * delta * delta);
    }
    __syncthreads();
    if (d == 0) {
        float s = 0.f;
        #pragma unroll
        for (int h = 0; h < TIME_BINS; h++) s += w[h];
        sinv = 1.0f / (s + 1e-8f);
    }
    __syncthreads();
    float inv3 = sinv * (1.0f / 3.0f);
    float v = 0.f;
    const int* base = &uh3[u * TIME_BINS * 3];
    #pragma unroll 4
    for (int h = 0; h < TIME_BINS; h++) {
        int c0 = base[h * 3 + 0], c1 = base[h * 3 + 1], c2 = base[h * 3 + 2];
        float e = cat_emb[c0 * 64 + d] + cat_emb[c1 * 64 + d] + cat_emb[c2 * 64 + d];
        v += w[h] * e;
    }
    v *= inv3;
    Q[b * 128 + d]      = 0.25f * acc[u * LATENT + d];
    Q[b * 128 + 64 + d] = ALPHA * v;
}

// ---------------- items: IT[m] = [0.25*acc[N_USERS+m] | cat_emb[item_cat[m]]] ----------------
__global__ void k_items(const float* __restrict__ acc,
                        const float* __restrict__ cat_emb,
                        const int*   __restrict__ item_cat,
                        float*       __restrict__ IT) {
    int g = blockIdx.x * blockDim.x + threadIdx.x;
    int m = g >> 6;
    int d = g & 63;
    if (m < M_PAD) {
        if (m < M_ITEMS) {
            IT[m * 128 + d]      = 0.25f * acc[(N_USERS + m) * LATENT + d];
            IT[m * 128 + 64 + d] = cat_emb[item_cat[m] * 64 + d];
        } else {
            IT[m * 128 + d] = 0.f;
            IT[m * 128 + 64 + d] = 0.f;
        }
    }
}

// ---------------- GEMM: C[1024,50000] = Q[1024,128] @ IT[M_PAD,128]^T, f32x2 ----------------
#define BM 128
#define BN 128
#define BK 8
#define TM 8
#define TN 8

__global__ __launch_bounds__(256) void k_gemm(const float* __restrict__ A,
                                              const float* __restrict__ B,
                                              float* __restrict__ C) {
    __shared__ __align__(16) float As[BK][BM];
    __shared__ __align__(16) float Bs[BK][BN];
    const int tid  = threadIdx.x;
    const int row0 = blockIdx.y * BM;   // batch offset
    const int col0 = blockIdx.x * BN;   // item offset
    const int ty   = tid / 16;
    const int tx   = tid % 16;

    ull acc[TM][TN / 2];
    #pragma unroll
    for (int i = 0; i < TM; i++)
        #pragma unroll
        for (int j = 0; j < TN / 2; j++) acc[i][j] = 0ull;

    const int lr = tid >> 1;          // 0..127
    const int lk = (tid & 1) * 4;     // 0 or 4

    #pragma unroll 1
    for (int k0 = 0; k0 < 128; k0 += BK) {
        float4 av = *(const float4*)(A + (row0 + lr) * 128 + k0 + lk);
        float4 bv = *(const float4*)(B + (col0 + lr) * 128 + k0 + lk);
        As[lk + 0][lr] = av.x; As[lk + 1][lr] = av.y;
        As[lk + 2][lr] = av.z; As[lk + 3][lr] = av.w;
        Bs[lk + 0][lr] = bv.x; Bs[lk + 1][lr] = bv.y;
        Bs[lk + 2][lr] = bv.z; Bs[lk + 3][lr] = bv.w;
        __syncthreads();
        #pragma unroll
        for (int kk = 0; kk < BK; kk++) {
            float4 a0 = *(const float4*)&As[kk][ty * TM];
            float4 a1 = *(const float4*)&As[kk][ty * TM + 4];
            ulonglong2 bp0 = *(const ulonglong2*)&Bs[kk][tx * TN];
            ulonglong2 bp1 = *(const ulonglong2*)&Bs[kk][tx * TN + 4];
            ull ap[TM];
            ap[0] = dup2(a0.x); ap[1] = dup2(a0.y); ap[2] = dup2(a0.z); ap[3] = dup2(a0.w);
            ap[4] = dup2(a1.x); ap[5] = dup2(a1.y); ap[6] = dup2(a1.z); ap[7] = dup2(a1.w);
            #pragma unroll
            for (int i = 0; i < TM; i++) {
                fma2(acc[i][0], ap[i], bp0.x);
                fma2(acc[i][1], ap[i], bp0.y);
                fma2(acc[i][2], ap[i], bp1.x);
                fma2(acc[i][3], ap[i], bp1.y);
            }
        }
        __syncthreads();
    }

    // store (50000 % 4 == 0 so float4 never straddles the valid edge)
    #pragma unroll
    for (int i = 0; i < TM; i++) {
        int r = row0 + ty * TM + i;            // always < 1024
        #pragma unroll
        for (int j = 0; j < TN / 2; j += 2) {
            int c = col0 + tx * TN + j * 2;
            if (c < M_ITEMS) {
                float2 v0 = unpack2(acc[i][j]);
                float2 v1 = unpack2(acc[i][j + 1]);
                *(float4*)(C + (size_t)r * M_ITEMS + c) = make_float4(v0.x, v0.y, v1.x, v1.y);
            }
        }
    }
}

// ---------------- launch ----------------
extern "C" void kernel_launch(void* const* d_in, const int* in_sizes, int n_in,
                              void* d_out, int out_size) {
    const float* user_emb  = (const float*)d_in[0];
    const float* item_emb  = (const float*)d_in[1];
    const float* cat_emb   = (const float*)d_in[2];
    const float* graph_vals= (const float*)d_in[3];
    const int*   graph_rows= (const int*)  d_in[4];
    const int*   graph_cols= (const int*)  d_in[5];
    const int*   uh3       = (const int*)  d_in[6];
    const int*   item_cat  = (const int*)  d_in[7];
    const int*   users     = (const int*)  d_in[8];
    const float* thetas    = (const float*)d_in[9];
    float* out = (float*)d_out;

    float *d_e0, *d_e1, *d_acc, *d_Q, *d_item;
    int2* d_edge; int *d_cnt, *d_rowstart, *d_cursor, *d_blocksums;
    unsigned char* d_need;
    cudaGetSymbolAddress((void**)&d_e0,       g_e0);
    cudaGetSymbolAddress((void**)&d_e1,       g_e1);
    cudaGetSymbolAddress((void**)&d_acc,      g_acc);
    cudaGetSymbolAddress((void**)&d_Q,        g_Q);
    cudaGetSymbolAddress((void**)&d_item,     g_item);
    cudaGetSymbolAddress((void**)&d_edge,     g_edge);
    cudaGetSymbolAddress((void**)&d_cnt,      g_cnt);
    cudaGetSymbolAddress((void**)&d_rowstart, g_rowstart);
    cudaGetSymbolAddress((void**)&d_cursor,   g_cursor);
    cudaGetSymbolAddress((void**)&d_blocksums,g_blocksums);
    cudaGetSymbolAddress((void**)&d_need,     g_need);

    // ---- CSR build (once; reused by all 3 layers) ----
    cudaMemsetAsync(d_cnt, 0, (size_t)N_NODES * sizeof(int), 0);
    cudaMemsetAsync(d_need, 0, (size_t)N_USERS, 0);
    k_count<<<(NNZ + 255) / 256, 256>>>(graph_rows, d_cnt);
    k_scan_blocks<<<NBLK, 256>>>(d_cnt, d_rowstart, d_blocksums);
    k_scan_sums<<<1, 32>>>(d_blocksums);
    k_add_offsets<<<(N_NODES + 255) / 256, 256>>>(d_rowstart, d_blocksums, d_cursor);
    k_fill<<<(NNZ + 255) / 256, 256>>>(graph_vals, graph_rows, graph_cols, d_cursor, d_edge);
    k_setflags<<<(BATCH + 255) / 256, 256>>>(users, d_need);

    // ---- init embeddings ----
    {
        int total = N_NODES * (LATENT / 4);
        k_init<<<(total + 255) / 256, 256>>>(user_emb, item_emb, d_e0, d_acc);
    }

    // ---- 3 LightGCN layers: atomic-free gather, fused accumulate ----
    {
        int th = N_NODES * 16;
        int blocks = (th + 255) / 256;
        k_gather<<<blocks, 256>>>(d_edge, d_rowstart, d_cnt, d_e0, d_e1, d_acc, d_need, 1, 0);
        k_gather<<<blocks, 256>>>(d_edge, d_rowstart, d_cnt, d_e1, d_e0, d_acc, d_need, 1, 0);
        k_gather<<<blocks, 256>>>(d_edge, d_rowstart, d_cnt, d_e0, d_e1, d_acc, d_need, 0, 1);
    }

    // ---- Q side ----
    k_clock<<<BATCH, 64>>>(d_acc, cat_emb, uh3, users, thetas, d_Q);

    // ---- item side ----
    {
        int total = M_PAD * 64;
        k_items<<<(total + 255) / 256, 256>>>(d_acc, cat_emb, item_cat, d_item);
    }

    // ---- f32x2 GEMM ----
    {
        dim3 grid(M_PAD / BN, BATCH / BM);
        k_gemm<<<grid, 256>>>(d_Q, d_item, out);
    }
}

// round 6
// speedup vs baseline: 1.3739x; 1.1002x over previous
#include <cuda_runtime.h>
#include <cuda_fp16.h>
#include <math_constants.h>
#include <cstdint>

#define N_USERS   100000
#define M_ITEMS   50000
#define N_NODES   (N_USERS + M_ITEMS)
#define LATENT    64
#define N_CATS    1000
#define N_LAYERS  3
#define TIME_BINS 24
#define NNZ       4800000
#define BATCH     1024
#define ALPHA     0.5f
#define M_PAD     50048          // 391 * 128

#define NODEF (N_NODES * LATENT)   // 9.6M elements
#define SCAN_CHUNK 1024
#define NBLK ((N_NODES + SCAN_CHUNK - 1) / SCAN_CHUNK)   // 147

typedef unsigned long long ull;

// ---------------- device scratch (static: no allocs allowed) ----------------
__device__ __align__(16) __half g_h0[NODEF];
__device__ __align__(16) __half g_h1[NODEF];
__device__ float g_acc[NODEF];
__device__ float g_Q[BATCH * 128];
__device__ float g_item[M_PAD * 128];
__device__ int2  g_edge[NNZ];          // (val bits, col) reordered by row
__device__ int   g_cnt[N_NODES];
__device__ int   g_rowstart[N_NODES];
__device__ int   g_cursor[N_NODES];
__device__ int   g_blocksums[NBLK];
__device__ unsigned char g_need[N_USERS];

// ---------------- f32x2 helpers ----------------
__device__ __forceinline__ ull dup2(float x) {
    ull p;
    asm("mov.b64 %0, {%1, %1};" : "=l"(p) : "f"(x));
    return p;
}
__device__ __forceinline__ void fma2(ull& c, ull a, ull b) {
    asm("fma.rn.f32x2 %0, %1, %2, %0;" : "+l"(c) : "l"(a), "l"(b));
}
__device__ __forceinline__ float2 unpack2(ull p) {
    float2 v;
    asm("mov.b64 {%0, %1}, %2;" : "=f"(v.x), "=f"(v.y) : "l"(p));
    return v;
}

// ---------------- init: acc = concat(user_emb, item_emb); h0 = fp16(acc) ----------------
__global__ void k_init(const float* __restrict__ ue, const float* __restrict__ ie,
                       __half* __restrict__ h0, float* __restrict__ acc) {
    int i = blockIdx.x * blockDim.x + threadIdx.x;       // float4 index
    const int total = N_NODES * (LATENT / 4);
    const int usplit = N_USERS * (LATENT / 4);
    if (i < total) {
        float4 v = (i < usplit) ? ((const float4*)ue)[i]
                                : ((const float4*)ie)[i - usplit];
        ((float4*)acc)[i] = v;
        half2 a = __floats2half2_rn(v.x, v.y);
        half2 b = __floats2half2_rn(v.z, v.w);
        ((half2*)h0)[i * 2]     = a;
        ((half2*)h0)[i * 2 + 1] = b;
    }
}

// ---------------- CSR build ----------------
__global__ void k_count(const int* __restrict__ rows, int* __restrict__ cnt) {
    int e = blockIdx.x * blockDim.x + threadIdx.x;
    if (e < NNZ) atomicAdd(&cnt[rows[e]], 1);
}

__global__ __launch_bounds__(256) void k_scan_blocks(const int* __restrict__ cnt,
                                                     int* __restrict__ rowstart,
                                                     int* __restrict__ blocksums) {
    __shared__ int wsum[8];
    __shared__ int woff[8];
    int tid  = threadIdx.x;
    int lane = tid & 31;
    int warp = tid >> 5;
    int base = blockIdx.x * SCAN_CHUNK + tid * 4;

    int c0 = 0, c1 = 0, c2 = 0, c3 = 0;
    if (base + 3 < N_NODES) {
        int4 c = *(const int4*)(cnt + base);
        c0 = c.x; c1 = c.y; c2 = c.z; c3 = c.w;
    } else {
        if (base + 0 < N_NODES) c0 = cnt[base + 0];
        if (base + 1 < N_NODES) c1 = cnt[base + 1];
        if (base + 2 < N_NODES) c2 = cnt[base + 2];
        if (base + 3 < N_NODES) c3 = cnt[base + 3];
    }
    int tsum = c0 + c1 + c2 + c3;

    int inc = tsum;
    #pragma unroll
    for (int off = 1; off < 32; off <<= 1) {
        int n = __shfl_up_sync(0xffffffffu, inc, off);
        if (lane >= off) inc += n;
    }
    if (lane == 31) wsum[warp] = inc;
    __syncthreads();
    if (tid == 0) {
        int r = 0;
        #pragma unroll
        for (int i = 0; i < 8; i++) { woff[i] = r; r += wsum[i]; }
        blocksums[blockIdx.x] = r;
    }
    __syncthreads();

    int excl = woff[warp] + (inc - tsum);
    if (base + 0 < N_NODES) rowstart[base + 0] = excl;
    if (base + 1 < N_NODES) rowstart[base + 1] = excl + c0;
    if (base + 2 < N_NODES) rowstart[base + 2] = excl + c0 + c1;
    if (base + 3 < N_NODES) rowstart[base + 3] = excl + c0 + c1 + c2;
}

__global__ void k_scan_sums(int* __restrict__ blocksums) {
    if (threadIdx.x == 0 && blockIdx.x == 0) {
        int r = 0;
        for (int i = 0; i < NBLK; i++) { int v = blocksums[i]; blocksums[i] = r; r += v; }
    }
}

__global__ void k_add_offsets(int* __restrict__ rowstart,
                              const int* __restrict__ blocksums,
                              int* __restrict__ cursor) {
    int i = blockIdx.x * blockDim.x + threadIdx.x;
    if (i < N_NODES) {
        int r = rowstart[i] + blocksums[i / SCAN_CHUNK];
        rowstart[i] = r;
        cursor[i]   = r;
    }
}

__global__ void k_fill(const float* __restrict__ vals,
                       const int*   __restrict__ rows,
                       const int*   __restrict__ cols,
                       int* __restrict__ cursor,
                       int2* __restrict__ edge) {
    int e = blockIdx.x * blockDim.x + threadIdx.x;
    if (e < NNZ) {
        int r = rows[e];
        int pos = atomicAdd(&cursor[r], 1);
        edge[pos] = make_int2(__float_as_int(vals[e]), cols[e]);
    }
}

__global__ void k_setflags(const int* __restrict__ users, unsigned char* __restrict__ need) {
    int i = blockIdx.x * blockDim.x + threadIdx.x;
    if (i < BATCH) need[users[i]] = 1;
}

// ---------------- layer: fp16 segment gather, fp32 accumulate, fused acc += s ----------------
// 8 lanes per row; each lane owns 8 dims (16 B fp16 per neighbor row).
__global__ __launch_bounds__(256) void k_gather(const int2* __restrict__ edge,
                                                const int*  __restrict__ rowstart,
                                                const int*  __restrict__ cnt,
                                                const __half* __restrict__ esrc,
                                                __half*       __restrict__ edst,
                                                float*        __restrict__ acc,
                                                const unsigned char* __restrict__ need,
                                                int writeE, int selective) {
    int g   = blockIdx.x * blockDim.x + threadIdx.x;
    int row = g >> 3;
    int t   = g & 7;
    if (row >= N_NODES) return;
    if (selective && row < N_USERS && !need[row]) return;
    unsigned gmask = 0xFFu << (threadIdx.x & 24);   // own 8-lane group

    int start = rowstart[row];
    int deg   = cnt[row];
    float s0 = 0.f, s1 = 0.f, s2 = 0.f, s3 = 0.f;
    float s4 = 0.f, s5 = 0.f, s6 = 0.f, s7 = 0.f;

    for (int base = 0; base < deg; base += 8) {
        int rem = deg - base;
        int2 ev = (t < rem) ? __ldg(&edge[start + base + t]) : make_int2(0, 0);
        int lim = rem < 8 ? rem : 8;
        #pragma unroll 4
        for (int k = 0; k < lim; k++) {
            float v = __int_as_float(__shfl_sync(gmask, ev.x, k, 8));
            int   c = __shfl_sync(gmask, ev.y, k, 8);
            uint4 m = __ldg((const uint4*)(esrc + (size_t)c * LATENT + t * 8));
            float2 f0 = __half22float2(*(half2*)&m.x);
            float2 f1 = __half22float2(*(half2*)&m.y);
            float2 f2 = __half22float2(*(half2*)&m.z);
            float2 f3 = __half22float2(*(half2*)&m.w);
            s0 += v * f0.x; s1 += v * f0.y;
            s2 += v * f1.x; s3 += v * f1.y;
            s4 += v * f2.x; s5 += v * f2.y;
            s6 += v * f3.x; s7 += v * f3.y;
        }
    }

    size_t idx = (size_t)row * LATENT + t * 8;
    // acc += s (fp32)
    float4 a0 = *(float4*)(acc + idx);
    float4 a1 = *(float4*)(acc + idx + 4);
    a0.x += s0; a0.y += s1; a0.z += s2; a0.w += s3;
    a1.x += s4; a1.y += s5; a1.z += s6; a1.w += s7;
    *(float4*)(acc + idx)     = a0;
    *(float4*)(acc + idx + 4) = a1;
    if (writeE) {
        uint4 o;
        *(half2*)&o.x = __floats2half2_rn(s0, s1);
        *(half2*)&o.y = __floats2half2_rn(s2, s3);
        *(half2*)&o.z = __floats2half2_rn(s4, s5);
        *(half2*)&o.w = __floats2half2_rn(s6, s7);
        *(uint4*)(edst + idx) = o;
    }
}

// ---------------- clock: build Q[b] = [0.25*acc[user] | alpha * v_clock] ----------------
__global__ void k_clock(const float* __restrict__ acc,
                        const float* __restrict__ cat_emb,
                        const int*   __restrict__ uh3,
                        const int*   __restrict__ users,
                        const float* __restrict__ thetas,
                        float*       __restrict__ Q) {
    int b = blockIdx.x;
    int d = threadIdx.x;       // 64 threads
    __shared__ float w[TIME_BINS];
    __shared__ float sinv;
    int u = users[b];
    if (d < TIME_BINS) {
        float cur = thetas[b] * (float)(TIME_BINS / (2.0 * CUDART_PI));
        float diff = fabsf(cur - (float)d);
        float delta = fminf(diff, (float)TIME_BINS - diff);
        w[d] = __expf(-0.5f * delta * delta);
    }
    __syncthreads();
    if (d == 0) {
        float s = 0.f;
        #pragma unroll
        for (int h = 0; h < TIME_BINS; h++) s += w[h];
        sinv = 1.0f / (s + 1e-8f);
    }
    __syncthreads();
    float inv3 = sinv * (1.0f / 3.0f);
    float v = 0.f;
    const int* base = &uh3[u * TIME_BINS * 3];
    #pragma unroll 4
    for (int h = 0; h < TIME_BINS; h++) {
        int c0 = base[h * 3 + 0], c1 = base[h * 3 + 1], c2 = base[h * 3 + 2];
        float e = cat_emb[c0 * 64 + d] + cat_emb[c1 * 64 + d] + cat_emb[c2 * 64 + d];
        v += w[h] * e;
    }
    v *= inv3;
    Q[b * 128 + d]      = 0.25f * acc[u * LATENT + d];
    Q[b * 128 + 64 + d] = ALPHA * v;
}

// ---------------- items: IT[m] = [0.25*acc[N_USERS+m] | cat_emb[item_cat[m]]] ----------------
__global__ void k_items(const float* __restrict__ acc,
                        const float* __restrict__ cat_emb,
                        const int*   __restrict__ item_cat,
                        float*       __restrict__ IT) {
    int g = blockIdx.x * blockDim.x + threadIdx.x;
    int m = g >> 6;
    int d = g & 63;
    if (m < M_PAD) {
        if (m < M_ITEMS) {
            IT[m * 128 + d]      = 0.25f * acc[(N_USERS + m) * LATENT + d];
            IT[m * 128 + 64 + d] = cat_emb[item_cat[m] * 64 + d];
        } else {
            IT[m * 128 + d] = 0.f;
            IT[m * 128 + 64 + d] = 0.f;
        }
    }
}

// ---------------- GEMM: C[1024,50000] = Q[1024,128] @ IT[M_PAD,128]^T, f32x2 ----------------
#define BM 128
#define BN 128
#define BK 8
#define TM 8
#define TN 8

__global__ __launch_bounds__(256) void k_gemm(const float* __restrict__ A,
                                              const float* __restrict__ B,
                                              float* __restrict__ C) {
    __shared__ __align__(16) float As[BK][BM];
    __shared__ __align__(16) float Bs[BK][BN];
    const int tid  = threadIdx.x;
    const int row0 = blockIdx.y * BM;   // batch offset
    const int col0 = blockIdx.x * BN;   // item offset
    const int ty   = tid / 16;
    const int tx   = tid % 16;

    ull acc[TM][TN / 2];
    #pragma unroll
    for (int i = 0; i < TM; i++)
        #pragma unroll
        for (int j = 0; j < TN / 2; j++) acc[i][j] = 0ull;

    const int lr = tid >> 1;          // 0..127
    const int lk = (tid & 1) * 4;     // 0 or 4

    #pragma unroll 1
    for (int k0 = 0; k0 < 128; k0 += BK) {
        float4 av = *(const float4*)(A + (row0 + lr) * 128 + k0 + lk);
        float4 bv = *(const float4*)(B + (col0 + lr) * 128 + k0 + lk);
        As[lk + 0][lr] = av.x; As[lk + 1][lr] = av.y;
        As[lk + 2][lr] = av.z; As[lk + 3][lr] = av.w;
        Bs[lk + 0][lr] = bv.x; Bs[lk + 1][lr] = bv.y;
        Bs[lk + 2][lr] = bv.z; Bs[lk + 3][lr] = bv.w;
        __syncthreads();
        #pragma unroll
        for (int kk = 0; kk < BK; kk++) {
            float4 a0 = *(const float4*)&As[kk][ty * TM];
            float4 a1 = *(const float4*)&As[kk][ty * TM + 4];
            ulonglong2 bp0 = *(const ulonglong2*)&Bs[kk][tx * TN];
            ulonglong2 bp1 = *(const ulonglong2*)&Bs[kk][tx * TN + 4];
            ull ap[TM];
            ap[0] = dup2(a0.x); ap[1] = dup2(a0.y); ap[2] = dup2(a0.z); ap[3] = dup2(a0.w);
            ap[4] = dup2(a1.x); ap[5] = dup2(a1.y); ap[6] = dup2(a1.z); ap[7] = dup2(a1.w);
            #pragma unroll
            for (int i = 0; i < TM; i++) {
                fma2(acc[i][0], ap[i], bp0.x);
                fma2(acc[i][1], ap[i], bp0.y);
                fma2(acc[i][2], ap[i], bp1.x);
                fma2(acc[i][3], ap[i], bp1.y);
            }
        }
        __syncthreads();
    }

    // store (50000 % 4 == 0 so float4 never straddles the valid edge)
    #pragma unroll
    for (int i = 0; i < TM; i++) {
        int r = row0 + ty * TM + i;            // always < 1024
        #pragma unroll
        for (int j = 0; j < TN / 2; j += 2) {
            int c = col0 + tx * TN + j * 2;
            if (c < M_ITEMS) {
                float2 v0 = unpack2(acc[i][j]);
                float2 v1 = unpack2(acc[i][j + 1]);
                *(float4*)(C + (size_t)r * M_ITEMS + c) = make_float4(v0.x, v0.y, v1.x, v1.y);
            }
        }
    }
}

// ---------------- launch ----------------
extern "C" void kernel_launch(void* const* d_in, const int* in_sizes, int n_in,
                              void* d_out, int out_size) {
    const float* user_emb  = (const float*)d_in[0];
    const float* item_emb  = (const float*)d_in[1];
    const float* cat_emb   = (const float*)d_in[2];
    const float* graph_vals= (const float*)d_in[3];
    const int*   graph_rows= (const int*)  d_in[4];
    const int*   graph_cols= (const int*)  d_in[5];
    const int*   uh3       = (const int*)  d_in[6];
    const int*   item_cat  = (const int*)  d_in[7];
    const int*   users     = (const int*)  d_in[8];
    const float* thetas    = (const float*)d_in[9];
    float* out = (float*)d_out;

    __half *d_h0, *d_h1;
    float *d_acc, *d_Q, *d_item;
    int2* d_edge; int *d_cnt, *d_rowstart, *d_cursor, *d_blocksums;
    unsigned char* d_need;
    cudaGetSymbolAddress((void**)&d_h0,       g_h0);
    cudaGetSymbolAddress((void**)&d_h1,       g_h1);
    cudaGetSymbolAddress((void**)&d_acc,      g_acc);
    cudaGetSymbolAddress((void**)&d_Q,        g_Q);
    cudaGetSymbolAddress((void**)&d_item,     g_item);
    cudaGetSymbolAddress((void**)&d_edge,     g_edge);
    cudaGetSymbolAddress((void**)&d_cnt,      g_cnt);
    cudaGetSymbolAddress((void**)&d_rowstart, g_rowstart);
    cudaGetSymbolAddress((void**)&d_cursor,   g_cursor);
    cudaGetSymbolAddress((void**)&d_blocksums,g_blocksums);
    cudaGetSymbolAddress((void**)&d_need,     g_need);

    // ---- CSR build (once; reused by all 3 layers) ----
    cudaMemsetAsync(d_cnt, 0, (size_t)N_NODES * sizeof(int), 0);
    cudaMemsetAsync(d_need, 0, (size_t)N_USERS, 0);
    k_count<<<(NNZ + 255) / 256, 256>>>(graph_rows, d_cnt);
    k_scan_blocks<<<NBLK, 256>>>(d_cnt, d_rowstart, d_blocksums);
    k_scan_sums<<<1, 32>>>(d_blocksums);
    k_add_offsets<<<(N_NODES + 255) / 256, 256>>>(d_rowstart, d_blocksums, d_cursor);
    k_fill<<<(NNZ + 255) / 256, 256>>>(graph_vals, graph_rows, graph_cols, d_cursor, d_edge);
    k_setflags<<<(BATCH + 255) / 256, 256>>>(users, d_need);

    // ---- init embeddings ----
    {
        int total = N_NODES * (LATENT / 4);
        k_init<<<(total + 255) / 256, 256>>>(user_emb, item_emb, d_h0, d_acc);
    }

    // ---- 3 LightGCN layers: fp16 gather, fp32 accumulate ----
    {
        int th = N_NODES * 8;
        int blocks = (th + 255) / 256;
        k_gather<<<blocks, 256>>>(d_edge, d_rowstart, d_cnt, d_h0, d_h1, d_acc, d_need, 1, 0);
        k_gather<<<blocks, 256>>>(d_edge, d_rowstart, d_cnt, d_h1, d_h0, d_acc, d_need, 1, 0);
        k_gather<<<blocks, 256>>>(d_edge, d_rowstart, d_cnt, d_h0, d_h1, d_acc, d_need, 0, 1);
    }

    // ---- Q side ----
    k_clock<<<BATCH, 64>>>(d_acc, cat_emb, uh3, users, thetas, d_Q);

    // ---- item side ----
    {
        int total = M_PAD * 64;
        k_items<<<(total + 255) / 256, 256>>>(d_acc, cat_emb, item_cat, d_item);
    }

    // ---- f32x2 GEMM ----
    {
        dim3 grid(M_PAD / BN, BATCH / BM);
        k_gemm<<<grid, 256>>>(d_Q, d_item, out);
    }
}

// round 7
// speedup vs baseline: 1.5366x; 1.1184x over previous
#include <cuda_runtime.h>
#include <cuda_fp16.h>
#include <math_constants.h>
#include <cstdint>

#define N_USERS   100000
#define M_ITEMS   50000
#define N_NODES   (N_USERS + M_ITEMS)
#define LATENT    64
#define N_CATS    1000
#define N_LAYERS  3
#define TIME_BINS 24
#define NNZ       4800000
#define BATCH     1024
#define ALPHA     0.5f
#define M_PAD     50048          // 391 * 128

#define NODEF (N_NODES * LATENT)   // 9.6M elements
#define SCAN_CHUNK 1024
#define NBLK ((N_NODES + SCAN_CHUNK - 1) / SCAN_CHUNK)   // 147

typedef unsigned long long ull;

// ---------------- device scratch (static: no allocs allowed) ----------------
__device__ __align__(16) __half g_h0[NODEF];
__device__ __align__(16) __half g_h1[NODEF];
__device__ float g_acc[NODEF];
__device__ float g_Vc[BATCH * 64];
__device__ float g_CT[N_CATS * BATCH];   // CT[cat][b], 4.1 MB
__device__ int2  g_edge[NNZ];            // (val bits, col) reordered by row
__device__ int   g_cnt[N_NODES];
__device__ int   g_rowstart[N_NODES];
__device__ int   g_cursor[N_NODES];
__device__ int   g_blocksums[NBLK];
__device__ unsigned char g_need[N_USERS];

// ---------------- f32x2 helpers ----------------
__device__ __forceinline__ ull dup2(float x) {
    ull p;
    asm("mov.b64 %0, {%1, %1};" : "=l"(p) : "f"(x));
    return p;
}
__device__ __forceinline__ void fma2(ull& c, ull a, ull b) {
    asm("fma.rn.f32x2 %0, %1, %2, %0;" : "+l"(c) : "l"(a), "l"(b));
}
__device__ __forceinline__ float2 unpack2(ull p) {
    float2 v;
    asm("mov.b64 {%0, %1}, %2;" : "=f"(v.x), "=f"(v.y) : "l"(p));
    return v;
}

// ---------------- init: acc = concat(emb); h0 = fp16(acc); zero cnt/need ----------------
__global__ void k_init(const float* __restrict__ ue, const float* __restrict__ ie,
                       __half* __restrict__ h0, float* __restrict__ acc,
                       int* __restrict__ cnt, unsigned char* __restrict__ need) {
    int i = blockIdx.x * blockDim.x + threadIdx.x;       // float4 index
    const int total = N_NODES * (LATENT / 4);
    const int usplit = N_USERS * (LATENT / 4);
    if (i < total) {
        float4 v = (i < usplit) ? ((const float4*)ue)[i]
                                : ((const float4*)ie)[i - usplit];
        ((float4*)acc)[i] = v;
        ((half2*)h0)[i * 2]     = __floats2half2_rn(v.x, v.y);
        ((half2*)h0)[i * 2 + 1] = __floats2half2_rn(v.z, v.w);
    }
    if (i < N_NODES) cnt[i] = 0;
    if (i < N_USERS) need[i] = 0;
}

// ---------------- CSR build ----------------
__global__ void k_count(const int* __restrict__ rows, int* __restrict__ cnt) {
    int e = blockIdx.x * blockDim.x + threadIdx.x;
    if (e < NNZ) atomicAdd(&cnt[rows[e]], 1);
}

__global__ __launch_bounds__(256) void k_scan_blocks(const int* __restrict__ cnt,
                                                     int* __restrict__ rowstart,
                                                     int* __restrict__ blocksums) {
    __shared__ int wsum[8];
    __shared__ int woff[8];
    int tid  = threadIdx.x;
    int lane = tid & 31;
    int warp = tid >> 5;
    int base = blockIdx.x * SCAN_CHUNK + tid * 4;

    int c0 = 0, c1 = 0, c2 = 0, c3 = 0;
    if (base + 3 < N_NODES) {
        int4 c = *(const int4*)(cnt + base);
        c0 = c.x; c1 = c.y; c2 = c.z; c3 = c.w;
    } else {
        if (base + 0 < N_NODES) c0 = cnt[base + 0];
        if (base + 1 < N_NODES) c1 = cnt[base + 1];
        if (base + 2 < N_NODES) c2 = cnt[base + 2];
        if (base + 3 < N_NODES) c3 = cnt[base + 3];
    }
    int tsum = c0 + c1 + c2 + c3;

    int inc = tsum;
    #pragma unroll
    for (int off = 1; off < 32; off <<= 1) {
        int n = __shfl_up_sync(0xffffffffu, inc, off);
        if (lane >= off) inc += n;
    }
    if (lane == 31) wsum[warp] = inc;
    __syncthreads();
    if (tid == 0) {
        int r = 0;
        #pragma unroll
        for (int i = 0; i < 8; i++) { woff[i] = r; r += wsum[i]; }
        blocksums[blockIdx.x] = r;           // raw chunk sum
    }
    __syncthreads();

    int excl = woff[warp] + (inc - tsum);
    if (base + 0 < N_NODES) rowstart[base + 0] = excl;
    if (base + 1 < N_NODES) rowstart[base + 1] = excl + c0;
    if (base + 2 < N_NODES) rowstart[base + 2] = excl + c0 + c1;
    if (base + 3 < N_NODES) rowstart[base + 3] = excl + c0 + c1 + c2;
}

// add chunk-prefix (computed in-kernel from raw blocksums) + init cursor
__global__ __launch_bounds__(256) void k_add_offsets(int* __restrict__ rowstart,
                                                     const int* __restrict__ blocksums,
                                                     int* __restrict__ cursor) {
    __shared__ int s_off;
    int chunk = blockIdx.x >> 2;             // 4 blocks of 256 per 1024-chunk
    if (threadIdx.x < 32) {
        int v = 0;
        for (int j = threadIdx.x; j < chunk; j += 32) v += blocksums[j];
        #pragma unroll
        for (int o = 16; o; o >>= 1) v += __shfl_down_sync(0xffffffffu, v, o);
        if (threadIdx.x == 0) s_off = v;
    }
    __syncthreads();
    int i = blockIdx.x * 256 + threadIdx.x;
    if (i < N_NODES) {
        int r = rowstart[i] + s_off;
        rowstart[i] = r;
        cursor[i]   = r;
    }
}

__global__ void k_fill(const float* __restrict__ vals,
                       const int*   __restrict__ rows,
                       const int*   __restrict__ cols,
                       int* __restrict__ cursor,
                       int2* __restrict__ edge) {
    int e = blockIdx.x * blockDim.x + threadIdx.x;
    if (e < NNZ) {
        int r = rows[e];
        int pos = atomicAdd(&cursor[r], 1);
        edge[pos] = make_int2(__float_as_int(vals[e]), cols[e]);
    }
}

__global__ void k_setflags(const int* __restrict__ users, unsigned char* __restrict__ need) {
    int i = blockIdx.x * blockDim.x + threadIdx.x;
    if (i < BATCH) need[users[i]] = 1;
}

// ---------------- layer: fp16 segment gather, fp32 accumulate, fused acc += s ----------------
__global__ __launch_bounds__(256) void k_gather(const int2* __restrict__ edge,
                                                const int*  __restrict__ rowstart,
                                                const int*  __restrict__ cnt,
                                                const __half* __restrict__ esrc,
                                                __half*       __restrict__ edst,
                                                float*        __restrict__ acc,
                                                const unsigned char* __restrict__ need,
                                                int writeE, int selective) {
    int g   = blockIdx.x * blockDim.x + threadIdx.x;
    int row = g >> 3;
    int t   = g & 7;
    if (row >= N_NODES) return;
    if (selective && row < N_USERS && !need[row]) return;
    unsigned gmask = 0xFFu << (threadIdx.x & 24);   // own 8-lane group

    int start = rowstart[row];
    int deg   = cnt[row];
    float s0 = 0.f, s1 = 0.f, s2 = 0.f, s3 = 0.f;
    float s4 = 0.f, s5 = 0.f, s6 = 0.f, s7 = 0.f;

    for (int base = 0; base < deg; base += 8) {
        int rem = deg - base;
        int2 ev = (t < rem) ? __ldg(&edge[start + base + t]) : make_int2(0, 0);
        int lim = rem < 8 ? rem : 8;
        #pragma unroll 4
        for (int k = 0; k < lim; k++) {
            float v = __int_as_float(__shfl_sync(gmask, ev.x, k, 8));
            int   c = __shfl_sync(gmask, ev.y, k, 8);
            uint4 m = __ldg((const uint4*)(esrc + (size_t)c * LATENT + t * 8));
            float2 f0 = __half22float2(*(half2*)&m.x);
            float2 f1 = __half22float2(*(half2*)&m.y);
            float2 f2 = __half22float2(*(half2*)&m.z);
            float2 f3 = __half22float2(*(half2*)&m.w);
            s0 += v * f0.x; s1 += v * f0.y;
            s2 += v * f1.x; s3 += v * f1.y;
            s4 += v * f2.x; s5 += v * f2.y;
            s6 += v * f3.x; s7 += v * f3.y;
        }
    }

    size_t idx = (size_t)row * LATENT + t * 8;
    float4 a0 = *(float4*)(acc + idx);
    float4 a1 = *(float4*)(acc + idx + 4);
    a0.x += s0; a0.y += s1; a0.z += s2; a0.w += s3;
    a1.x += s4; a1.y += s5; a1.z += s6; a1.w += s7;
    *(float4*)(acc + idx)     = a0;
    *(float4*)(acc + idx + 4) = a1;
    if (writeE) {
        uint4 o;
        *(half2*)&o.x = __floats2half2_rn(s0, s1);
        *(half2*)&o.y = __floats2half2_rn(s2, s3);
        *(half2*)&o.z = __floats2half2_rn(s4, s5);
        *(half2*)&o.w = __floats2half2_rn(s6, s7);
        *(uint4*)(edst + idx) = o;
    }
}

// ---------------- v_clock only: Vc[b][64] ----------------
__global__ void k_vclock(const float* __restrict__ cat_emb,
                         const int*   __restrict__ uh3,
                         const int*   __restrict__ users,
                         const float* __restrict__ thetas,
                         float*       __restrict__ Vc) {
    int b = blockIdx.x;
    int d = threadIdx.x;       // 64 threads
    __shared__ float w[TIME_BINS];
    __shared__ float sinv;
    int u = users[b];
    if (d < TIME_BINS) {
        float cur = thetas[b] * (float)(TIME_BINS / (2.0 * CUDART_PI));
        float diff = fabsf(cur - (float)d);
        float delta = fminf(diff, (float)TIME_BINS - diff);
        w[d] = __expf(-0.5f * delta * delta);
    }
    __syncthreads();
    if (d == 0) {
        float s = 0.f;
        #pragma unroll
        for (int h = 0; h < TIME_BINS; h++) s += w[h];
        sinv = 1.0f / (s + 1e-8f);
    }
    __syncthreads();
    float inv3 = sinv * (1.0f / 3.0f);
    float v = 0.f;
    const int* base = &uh3[u * TIME_BINS * 3];
    #pragma unroll 4
    for (int h = 0; h < TIME_BINS; h++) {
        int c0 = base[h * 3 + 0], c1 = base[h * 3 + 1], c2 = base[h * 3 + 2];
        float e = cat_emb[c0 * 64 + d] + cat_emb[c1 * 64 + d] + cat_emb[c2 * 64 + d];
        v += w[h] * e;
    }
    Vc[b * 64 + d] = v * inv3;
}

// ---------------- clock table: CT[cat][b] = ALPHA * cat_emb[cat] . Vc[b] ----------------
#define CT_CATS 8
__global__ __launch_bounds__(256) void k_ct(const float* __restrict__ cat_emb,
                                            const float* __restrict__ Vc,
                                            float* __restrict__ CT) {
    __shared__ float sc[CT_CATS][64];
    int cat0 = blockIdx.y * CT_CATS;
    for (int i = threadIdx.x; i < CT_CATS * 64; i += 256) {
        int cc = cat0 + i / 64;
        sc[i / 64][i % 64] = (cc < N_CATS) ? cat_emb[cc * 64 + (i % 64)] : 0.f;
    }
    __syncthreads();
    int b = blockIdx.x * 256 + threadIdx.x;
    float acc[CT_CATS];
    #pragma unroll
    for (int c = 0; c < CT_CATS; c++) acc[c] = 0.f;
    #pragma unroll 4
    for (int k = 0; k < 64; k += 4) {
        float4 v = *(const float4*)(Vc + b * 64 + k);
        #pragma unroll
        for (int c = 0; c < CT_CATS; c++)
            acc[c] += v.x * sc[c][k] + v.y * sc[c][k + 1] + v.z * sc[c][k + 2] + v.w * sc[c][k + 3];
    }
    #pragma unroll
    for (int c = 0; c < CT_CATS; c++)
        if (cat0 + c < N_CATS) CT[(cat0 + c) * BATCH + b] = ALPHA * acc[c];
}

// ---------------- GEMM K=64: C[b][m] = 0.0625*(acc_u[b].acc_i[m]) + CT[cat[m]][b] ----------------
#define BM 128
#define BN 128
#define BK 8
#define TM 8
#define TN 8

__global__ __launch_bounds__(256) void k_gemm(const float* __restrict__ acc,
                                              const int*   __restrict__ users,
                                              const int*   __restrict__ item_cat,
                                              const float* __restrict__ CT,
                                              float* __restrict__ C) {
    __shared__ __align__(16) float As[BK][BM];
    __shared__ __align__(16) float Bs[BK][BN];
    const int tid  = threadIdx.x;
    const int row0 = blockIdx.y * BM;   // batch offset
    const int col0 = blockIdx.x * BN;   // item offset
    const int ty   = tid / 16;
    const int tx   = tid % 16;

    ull facc[TM][TN / 2];
    #pragma unroll
    for (int i = 0; i < TM; i++)
        #pragma unroll
        for (int j = 0; j < TN / 2; j++) facc[i][j] = 0ull;

    const int lr = tid >> 1;          // 0..127
    const int lk = (tid & 1) * 4;     // 0 or 4

    const int u = users[row0 + lr];
    const float* aptr = acc + (size_t)u * LATENT;
    const int bcol = col0 + lr;
    const bool bvalid = bcol < M_ITEMS;
    const float* bptr = acc + (size_t)(N_USERS + bcol) * LATENT;

    #pragma unroll 1
    for (int k0 = 0; k0 < LATENT; k0 += BK) {
        float4 av = *(const float4*)(aptr + k0 + lk);
        float4 bv = bvalid ? *(const float4*)(bptr + k0 + lk)
                           : make_float4(0.f, 0.f, 0.f, 0.f);
        As[lk + 0][lr] = av.x; As[lk + 1][lr] = av.y;
        As[lk + 2][lr] = av.z; As[lk + 3][lr] = av.w;
        Bs[lk + 0][lr] = bv.x; Bs[lk + 1][lr] = bv.y;
        Bs[lk + 2][lr] = bv.z; Bs[lk + 3][lr] = bv.w;
        __syncthreads();
        #pragma unroll
        for (int kk = 0; kk < BK; kk++) {
            float4 a0 = *(const float4*)&As[kk][ty * TM];
            float4 a1 = *(const float4*)&As[kk][ty * TM + 4];
            ulonglong2 bp0 = *(const ulonglong2*)&Bs[kk][tx * TN];
            ulonglong2 bp1 = *(const ulonglong2*)&Bs[kk][tx * TN + 4];
            ull ap[TM];
            ap[0] = dup2(a0.x); ap[1] = dup2(a0.y); ap[2] = dup2(a0.z); ap[3] = dup2(a0.w);
            ap[4] = dup2(a1.x); ap[5] = dup2(a1.y); ap[6] = dup2(a1.z); ap[7] = dup2(a1.w);
            #pragma unroll
            for (int i = 0; i < TM; i++) {
                fma2(facc[i][0], ap[i], bp0.x);
                fma2(facc[i][1], ap[i], bp0.y);
                fma2(facc[i][2], ap[i], bp1.x);
                fma2(facc[i][3], ap[i], bp1.y);
            }
        }
        __syncthreads();
    }

    // epilogue: scale + CT gather + store
    int cats[TN];
    #pragma unroll
    for (int j = 0; j < TN; j++) {
        int c = col0 + tx * TN + j;
        cats[j] = (c < M_ITEMS) ? __ldg(&item_cat[c]) : 0;
    }
    const float scale = 0.0625f;     // 0.25 (user layer-mean) * 0.25 (item layer-mean)
    #pragma unroll
    for (int i = 0; i < TM; i++) {
        int r = row0 + ty * TM + i;            // always < 1024
        float ct[TN];
        #pragma unroll
        for (int j = 0; j < TN; j++) ct[j] = __ldg(&CT[(size_t)cats[j] * BATCH + r]);
        #pragma unroll
        for (int j = 0; j < TN / 2; j += 2) {
            int c = col0 + tx * TN + j * 2;
            if (c < M_ITEMS) {
                float2 v0 = unpack2(facc[i][j]);
                float2 v1 = unpack2(facc[i][j + 1]);
                float4 o = make_float4(scale * v0.x + ct[j * 2 + 0],
                                       scale * v0.y + ct[j * 2 + 1],
                                       scale * v1.x + ct[j * 2 + 2],
                                       scale * v1.y + ct[j * 2 + 3]);
                *(float4*)(C + (size_t)r * M_ITEMS + c) = o;
            }
        }
    }
}

// ---------------- launch ----------------
extern "C" void kernel_launch(void* const* d_in, const int* in_sizes, int n_in,
                              void* d_out, int out_size) {
    const float* user_emb  = (const float*)d_in[0];
    const float* item_emb  = (const float*)d_in[1];
    const float* cat_emb   = (const float*)d_in[2];
    const float* graph_vals= (const float*)d_in[3];
    const int*   graph_rows= (const int*)  d_in[4];
    const int*   graph_cols= (const int*)  d_in[5];
    const int*   uh3       = (const int*)  d_in[6];
    const int*   item_cat  = (const int*)  d_in[7];
    const int*   users     = (const int*)  d_in[8];
    const float* thetas    = (const float*)d_in[9];
    float* out = (float*)d_out;

    __half *d_h0, *d_h1;
    float *d_acc, *d_Vc, *d_CT;
    int2* d_edge; int *d_cnt, *d_rowstart, *d_cursor, *d_blocksums;
    unsigned char* d_need;
    cudaGetSymbolAddress((void**)&d_h0,       g_h0);
    cudaGetSymbolAddress((void**)&d_h1,       g_h1);
    cudaGetSymbolAddress((void**)&d_acc,      g_acc);
    cudaGetSymbolAddress((void**)&d_Vc,       g_Vc);
    cudaGetSymbolAddress((void**)&d_CT,       g_CT);
    cudaGetSymbolAddress((void**)&d_edge,     g_edge);
    cudaGetSymbolAddress((void**)&d_cnt,      g_cnt);
    cudaGetSymbolAddress((void**)&d_rowstart, g_rowstart);
    cudaGetSymbolAddress((void**)&d_cursor,   g_cursor);
    cudaGetSymbolAddress((void**)&d_blocksums,g_blocksums);
    cudaGetSymbolAddress((void**)&d_need,     g_need);

    // launch order tuned so ncu (-s 5 -c 1) captures gather L1 (launch #6)
    // 1: init (also zeros cnt/need)
    {
        int total = N_NODES * (LATENT / 4);
        k_init<<<(total + 255) / 256, 256>>>(user_emb, item_emb, d_h0, d_acc, d_cnt, d_need);
    }
    // 2-5: CSR build
    k_count<<<(NNZ + 255) / 256, 256>>>(graph_rows, d_cnt);
    k_scan_blocks<<<NBLK, 256>>>(d_cnt, d_rowstart, d_blocksums);
    k_add_offsets<<<(N_NODES + SCAN_CHUNK - 1) / SCAN_CHUNK * 4, 256>>>(d_rowstart, d_blocksums, d_cursor);
    k_fill<<<(NNZ + 255) / 256, 256>>>(graph_vals, graph_rows, graph_cols, d_cursor, d_edge);

    // 6-9: LightGCN layers (L3 selective)
    {
        int th = N_NODES * 8;
        int blocks = (th + 255) / 256;
        k_gather<<<blocks, 256>>>(d_edge, d_rowstart, d_cnt, d_h0, d_h1, d_acc, d_need, 1, 0);  // #6
        k_gather<<<blocks, 256>>>(d_edge, d_rowstart, d_cnt, d_h1, d_h0, d_acc, d_need, 1, 0);  // #7
        k_setflags<<<(BATCH + 255) / 256, 256>>>(users, d_need);                                // #8
        k_gather<<<blocks, 256>>>(d_edge, d_rowstart, d_cnt, d_h0, d_h1, d_acc, d_need, 0, 1);  // #9
    }

    // 10-11: clock path
    k_vclock<<<BATCH, 64>>>(cat_emb, uh3, users, thetas, d_Vc);
    {
        dim3 grid(BATCH / 256, (N_CATS + CT_CATS - 1) / CT_CATS);
        k_ct<<<grid, 256>>>(cat_emb, d_Vc, d_CT);
    }

    // 12: fused GEMM (K=64) + CT gather epilogue
    {
        dim3 grid(M_PAD / BN, BATCH / BM);
        k_gemm<<<grid, 256>>>(d_acc, users, item_cat, d_CT, out);
    }
}

// round 8
// speedup vs baseline: 1.5749x; 1.0249x over previous
#include <cuda_runtime.h>
#include <cuda_fp16.h>
#include <math_constants.h>
#include <cstdint>

#define N_USERS   100000
#define M_ITEMS   50000
#define N_NODES   (N_USERS + M_ITEMS)
#define LATENT    64
#define N_CATS    1000
#define N_LAYERS  3
#define TIME_BINS 24
#define NNZ       4800000
#define BATCH     1024
#define ALPHA     0.5f
#define M_PAD     50048          // 391 * 128

#define NODEF (N_NODES * LATENT)   // 9.6M elements
#define SCAN_CHUNK 1024
#define NBLK ((N_NODES + SCAN_CHUNK - 1) / SCAN_CHUNK)   // 147

typedef unsigned long long ull;

// ---------------- device scratch (static: no allocs allowed) ----------------
__device__ __align__(16) __half g_h0[NODEF];
__device__ __align__(16) __half g_h1[NODEF];
__device__ float g_acc[NODEF];
__device__ float g_Vc[BATCH * 64];
__device__ float g_CT[N_CATS * BATCH];   // CT[cat][b], 4.1 MB
__device__ int2  g_edge[NNZ];            // (val bits, col) reordered by row
__device__ int   g_cnt[N_NODES];
__device__ int   g_rowstart[N_NODES];
__device__ int   g_cursor[N_NODES];
__device__ int   g_blocksums[NBLK];
__device__ unsigned char g_need[N_USERS];

// ---------------- f32x2 helpers ----------------
__device__ __forceinline__ ull dup2(float x) {
    ull p;
    asm("mov.b64 %0, {%1, %1};" : "=l"(p) : "f"(x));
    return p;
}
__device__ __forceinline__ void fma2(ull& c, ull a, ull b) {
    asm("fma.rn.f32x2 %0, %1, %2, %0;" : "+l"(c) : "l"(a), "l"(b));
}
__device__ __forceinline__ float2 unpack2(ull p) {
    float2 v;
    asm("mov.b64 {%0, %1}, %2;" : "=f"(v.x), "=f"(v.y) : "l"(p));
    return v;
}

// ---------------- init: h0 = fp16(concat(emb)); zero cnt/need (acc NOT written) ----------------
__global__ void k_init(const float* __restrict__ ue, const float* __restrict__ ie,
                       __half* __restrict__ h0,
                       int* __restrict__ cnt, unsigned char* __restrict__ need) {
    int i = blockIdx.x * blockDim.x + threadIdx.x;       // float4 index
    const int total = N_NODES * (LATENT / 4);
    const int usplit = N_USERS * (LATENT / 4);
    if (i < total) {
        float4 v = (i < usplit) ? ((const float4*)ue)[i]
                                : ((const float4*)ie)[i - usplit];
        ((half2*)h0)[i * 2]     = __floats2half2_rn(v.x, v.y);
        ((half2*)h0)[i * 2 + 1] = __floats2half2_rn(v.z, v.w);
    }
    if (i < N_NODES) cnt[i] = 0;
    if (i < N_USERS) need[i] = 0;
}

// ---------------- CSR build: count (4 edges/thread) ----------------
__global__ void k_count(const int* __restrict__ rows, int* __restrict__ cnt) {
    int e4 = blockIdx.x * blockDim.x + threadIdx.x;
    if (e4 < NNZ / 4) {
        int4 r = ((const int4*)rows)[e4];
        atomicAdd(&cnt[r.x], 1);
        atomicAdd(&cnt[r.y], 1);
        atomicAdd(&cnt[r.z], 1);
        atomicAdd(&cnt[r.w], 1);
    }
}

__global__ __launch_bounds__(256) void k_scan_blocks(const int* __restrict__ cnt,
                                                     int* __restrict__ rowstart,
                                                     int* __restrict__ blocksums) {
    __shared__ int wsum[8];
    __shared__ int woff[8];
    int tid  = threadIdx.x;
    int lane = tid & 31;
    int warp = tid >> 5;
    int base = blockIdx.x * SCAN_CHUNK + tid * 4;

    int c0 = 0, c1 = 0, c2 = 0, c3 = 0;
    if (base + 3 < N_NODES) {
        int4 c = *(const int4*)(cnt + base);
        c0 = c.x; c1 = c.y; c2 = c.z; c3 = c.w;
    } else {
        if (base + 0 < N_NODES) c0 = cnt[base + 0];
        if (base + 1 < N_NODES) c1 = cnt[base + 1];
        if (base + 2 < N_NODES) c2 = cnt[base + 2];
        if (base + 3 < N_NODES) c3 = cnt[base + 3];
    }
    int tsum = c0 + c1 + c2 + c3;

    int inc = tsum;
    #pragma unroll
    for (int off = 1; off < 32; off <<= 1) {
        int n = __shfl_up_sync(0xffffffffu, inc, off);
        if (lane >= off) inc += n;
    }
    if (lane == 31) wsum[warp] = inc;
    __syncthreads();
    if (tid == 0) {
        int r = 0;
        #pragma unroll
        for (int i = 0; i < 8; i++) { woff[i] = r; r += wsum[i]; }
        blocksums[blockIdx.x] = r;           // raw chunk sum
    }
    __syncthreads();

    int excl = woff[warp] + (inc - tsum);
    if (base + 0 < N_NODES) rowstart[base + 0] = excl;
    if (base + 1 < N_NODES) rowstart[base + 1] = excl + c0;
    if (base + 2 < N_NODES) rowstart[base + 2] = excl + c0 + c1;
    if (base + 3 < N_NODES) rowstart[base + 3] = excl + c0 + c1 + c2;
}

// add chunk-prefix + init cursor
__global__ __launch_bounds__(256) void k_add_offsets(int* __restrict__ rowstart,
                                                     const int* __restrict__ blocksums,
                                                     int* __restrict__ cursor) {
    __shared__ int s_off;
    int chunk = blockIdx.x >> 2;             // 4 blocks of 256 per 1024-chunk
    if (threadIdx.x < 32) {
        int v = 0;
        for (int j = threadIdx.x; j < chunk; j += 32) v += blocksums[j];
        #pragma unroll
        for (int o = 16; o; o >>= 1) v += __shfl_down_sync(0xffffffffu, v, o);
        if (threadIdx.x == 0) s_off = v;
    }
    __syncthreads();
    int i = blockIdx.x * 256 + threadIdx.x;
    if (i < N_NODES) {
        int r = rowstart[i] + s_off;
        rowstart[i] = r;
        cursor[i]   = r;
    }
}

// ---------------- CSR build: fill (4 edges/thread) ----------------
__global__ void k_fill(const float* __restrict__ vals,
                       const int*   __restrict__ rows,
                       const int*   __restrict__ cols,
                       int* __restrict__ cursor,
                       int2* __restrict__ edge) {
    int e4 = blockIdx.x * blockDim.x + threadIdx.x;
    if (e4 < NNZ / 4) {
        int4   r = ((const int4*)rows)[e4];
        int4   c = ((const int4*)cols)[e4];
        float4 v = ((const float4*)vals)[e4];
        int p;
        p = atomicAdd(&cursor[r.x], 1); edge[p] = make_int2(__float_as_int(v.x), c.x);
        p = atomicAdd(&cursor[r.y], 1); edge[p] = make_int2(__float_as_int(v.y), c.y);
        p = atomicAdd(&cursor[r.z], 1); edge[p] = make_int2(__float_as_int(v.z), c.z);
        p = atomicAdd(&cursor[r.w], 1); edge[p] = make_int2(__float_as_int(v.w), c.w);
    }
}

__global__ void k_setflags(const int* __restrict__ users, unsigned char* __restrict__ need) {
    int i = blockIdx.x * blockDim.x + threadIdx.x;
    if (i < BATCH) need[users[i]] = 1;
}

// ---------------- layer: fp16 segment gather, fp32 accumulate ----------------
// mode 0: acc += s, write edst       (middle layer)
// mode 1: acc  = emb[row] + s, write edst   (first layer; acc never read)
// mode 2: acc += s, no edst, selective rows (last layer)
__global__ __launch_bounds__(256) void k_gather(const int2* __restrict__ edge,
                                                const int*  __restrict__ rowstart,
                                                const int*  __restrict__ cnt,
                                                const __half* __restrict__ esrc,
                                                __half*       __restrict__ edst,
                                                float*        __restrict__ acc,
                                                const unsigned char* __restrict__ need,
                                                const float* __restrict__ ue,
                                                const float* __restrict__ ie,
                                                int mode) {
    int g   = blockIdx.x * blockDim.x + threadIdx.x;
    int row = g >> 3;
    int t   = g & 7;
    if (row >= N_NODES) return;
    if (mode == 2 && row < N_USERS && !need[row]) return;
    unsigned gmask = 0xFFu << (threadIdx.x & 24);   // own 8-lane group

    int start = rowstart[row];
    int deg   = cnt[row];
    float s0 = 0.f, s1 = 0.f, s2 = 0.f, s3 = 0.f;
    float s4 = 0.f, s5 = 0.f, s6 = 0.f, s7 = 0.f;

    for (int base = 0; base < deg; base += 8) {
        int rem = deg - base;
        int2 ev = (t < rem) ? __ldg(&edge[start + base + t]) : make_int2(0, 0);
        int lim = rem < 8 ? rem : 8;
        #pragma unroll 4
        for (int k = 0; k < lim; k++) {
            float v = __int_as_float(__shfl_sync(gmask, ev.x, k, 8));
            int   c = __shfl_sync(gmask, ev.y, k, 8);
            uint4 m = __ldg((const uint4*)(esrc + (size_t)c * LATENT + t * 8));
            float2 f0 = __half22float2(*(half2*)&m.x);
            float2 f1 = __half22float2(*(half2*)&m.y);
            float2 f2 = __half22float2(*(half2*)&m.z);
            float2 f3 = __half22float2(*(half2*)&m.w);
            s0 += v * f0.x; s1 += v * f0.y;
            s2 += v * f1.x; s3 += v * f1.y;
            s4 += v * f2.x; s5 += v * f2.y;
            s6 += v * f3.x; s7 += v * f3.y;
        }
    }

    size_t idx = (size_t)row * LATENT + t * 8;
    float4 a0, a1;
    if (mode == 1) {
        const float* emb = (row < N_USERS) ? (ue + (size_t)row * LATENT)
                                           : (ie + (size_t)(row - N_USERS) * LATENT);
        a0 = *(const float4*)(emb + t * 8);
        a1 = *(const float4*)(emb + t * 8 + 4);
    } else {
        a0 = *(float4*)(acc + idx);
        a1 = *(float4*)(acc + idx + 4);
    }
    a0.x += s0; a0.y += s1; a0.z += s2; a0.w += s3;
    a1.x += s4; a1.y += s5; a1.z += s6; a1.w += s7;
    *(float4*)(acc + idx)     = a0;
    *(float4*)(acc + idx + 4) = a1;
    if (mode != 2) {
        uint4 o;
        *(half2*)&o.x = __floats2half2_rn(s0, s1);
        *(half2*)&o.y = __floats2half2_rn(s2, s3);
        *(half2*)&o.z = __floats2half2_rn(s4, s5);
        *(half2*)&o.w = __floats2half2_rn(s6, s7);
        *(uint4*)(edst + idx) = o;
    }
}

// ---------------- v_clock only: Vc[b][64] ----------------
__global__ void k_vclock(const float* __restrict__ cat_emb,
                         const int*   __restrict__ uh3,
                         const int*   __restrict__ users,
                         const float* __restrict__ thetas,
                         float*       __restrict__ Vc) {
    int b = blockIdx.x;
    int d = threadIdx.x;       // 64 threads
    __shared__ float w[TIME_BINS];
    __shared__ float sinv;
    int u = users[b];
    if (d < TIME_BINS) {
        float cur = thetas[b] * (float)(TIME_BINS / (2.0 * CUDART_PI));
        float diff = fabsf(cur - (float)d);
        float delta = fminf(diff, (float)TIME_BINS - diff);
        w[d] = __expf(-0.5f * delta * delta);
    }
    __syncthreads();
    if (d == 0) {
        float s = 0.f;
        #pragma unroll
        for (int h = 0; h < TIME_BINS; h++) s += w[h];
        sinv = 1.0f / (s + 1e-8f);
    }
    __syncthreads();
    float inv3 = sinv * (1.0f / 3.0f);
    float v = 0.f;
    const int* base = &uh3[u * TIME_BINS * 3];
    #pragma unroll 4
    for (int h = 0; h < TIME_BINS; h++) {
        int c0 = base[h * 3 + 0], c1 = base[h * 3 + 1], c2 = base[h * 3 + 2];
        float e = cat_emb[c0 * 64 + d] + cat_emb[c1 * 64 + d] + cat_emb[c2 * 64 + d];
        v += w[h] * e;
    }
    Vc[b * 64 + d] = v * inv3;
}

// ---------------- clock table: CT[cat][b] = ALPHA * cat_emb[cat] . Vc[b] ----------------
#define CT_CATS 8
__global__ __launch_bounds__(256) void k_ct(const float* __restrict__ cat_emb,
                                            const float* __restrict__ Vc,
                                            float* __restrict__ CT) {
    __shared__ float sc[CT_CATS][64];
    int cat0 = blockIdx.y * CT_CATS;
    for (int i = threadIdx.x; i < CT_CATS * 64; i += 256) {
        int cc = cat0 + i / 64;
        sc[i / 64][i % 64] = (cc < N_CATS) ? cat_emb[cc * 64 + (i % 64)] : 0.f;
    }
    __syncthreads();
    int b = blockIdx.x * 256 + threadIdx.x;
    float acc[CT_CATS];
    #pragma unroll
    for (int c = 0; c < CT_CATS; c++) acc[c] = 0.f;
    #pragma unroll 4
    for (int k = 0; k < 64; k += 4) {
        float4 v = *(const float4*)(Vc + b * 64 + k);
        #pragma unroll
        for (int c = 0; c < CT_CATS; c++)
            acc[c] += v.x * sc[c][k] + v.y * sc[c][k + 1] + v.z * sc[c][k + 2] + v.w * sc[c][k + 3];
    }
    #pragma unroll
    for (int c = 0; c < CT_CATS; c++)
        if (cat0 + c < N_CATS) CT[(cat0 + c) * BATCH + b] = ALPHA * acc[c];
}

// ---------------- GEMM K=64, BK=16, register double-buffered ----------------
#define BM 128
#define BN 128
#define BK 16
#define TM 8
#define TN 8

__global__ __launch_bounds__(256, 2) void k_gemm(const float* __restrict__ acc,
                                                 const int*   __restrict__ users,
                                                 const int*   __restrict__ item_cat,
                                                 const float* __restrict__ CT,
                                                 float* __restrict__ C) {
    __shared__ __align__(16) float As[BK][BM];
    __shared__ __align__(16) float Bs[BK][BN];
    const int tid  = threadIdx.x;
    const int row0 = blockIdx.y * BM;   // batch offset
    const int col0 = blockIdx.x * BN;   // item offset
    const int ty   = tid / 16;
    const int tx   = tid % 16;

    ull facc[TM][TN / 2];
    #pragma unroll
    for (int i = 0; i < TM; i++)
        #pragma unroll
        for (int j = 0; j < TN / 2; j++) facc[i][j] = 0ull;

    const int lr = tid >> 1;          // 0..127
    const int lq = (tid & 1) * 8;     // 0 or 8 (8-float segment within BK=16)

    const int u = users[row0 + lr];
    const float* aptr = acc + (size_t)u * LATENT;
    const int bcol = col0 + lr;
    const bool bvalid = bcol < M_ITEMS;
    const float* bptr = acc + (size_t)(N_USERS + bcol) * LATENT;

    // prefetch k0 = 0
    float4 pa0 = *(const float4*)(aptr + lq);
    float4 pa1 = *(const float4*)(aptr + lq + 4);
    float4 pb0 = bvalid ? *(const float4*)(bptr + lq)     : make_float4(0.f, 0.f, 0.f, 0.f);
    float4 pb1 = bvalid ? *(const float4*)(bptr + lq + 4) : make_float4(0.f, 0.f, 0.f, 0.f);

    #pragma unroll
    for (int k0 = 0; k0 < LATENT; k0 += BK) {
        // stage into smem
        As[lq + 0][lr] = pa0.x; As[lq + 1][lr] = pa0.y; As[lq + 2][lr] = pa0.z; As[lq + 3][lr] = pa0.w;
        As[lq + 4][lr] = pa1.x; As[lq + 5][lr] = pa1.y; As[lq + 6][lr] = pa1.z; As[lq + 7][lr] = pa1.w;
        Bs[lq + 0][lr] = pb0.x; Bs[lq + 1][lr] = pb0.y; Bs[lq + 2][lr] = pb0.z; Bs[lq + 3][lr] = pb0.w;
        Bs[lq + 4][lr] = pb1.x; Bs[lq + 5][lr] = pb1.y; Bs[lq + 6][lr] = pb1.z; Bs[lq + 7][lr] = pb1.w;
        __syncthreads();

        // prefetch next tile (overlaps with compute below)
        if (k0 + BK < LATENT) {
            int kn = k0 + BK + lq;
            pa0 = *(const float4*)(aptr + kn);
            pa1 = *(const float4*)(aptr + kn + 4);
            pb0 = bvalid ? *(const float4*)(bptr + kn)     : make_float4(0.f, 0.f, 0.f, 0.f);
            pb1 = bvalid ? *(const float4*)(bptr + kn + 4) : make_float4(0.f, 0.f, 0.f, 0.f);
        }

        #pragma unroll
        for (int kk = 0; kk < BK; kk++) {
            float4 a0 = *(const float4*)&As[kk][ty * TM];
            float4 a1 = *(const float4*)&As[kk][ty * TM + 4];
            ulonglong2 bp0 = *(const ulonglong2*)&Bs[kk][tx * TN];
            ulonglong2 bp1 = *(const ulonglong2*)&Bs[kk][tx * TN + 4];
            ull ap[TM];
            ap[0] = dup2(a0.x); ap[1] = dup2(a0.y); ap[2] = dup2(a0.z); ap[3] = dup2(a0.w);
            ap[4] = dup2(a1.x); ap[5] = dup2(a1.y); ap[6] = dup2(a1.z); ap[7] = dup2(a1.w);
            #pragma unroll
            for (int i = 0; i < TM; i++) {
                fma2(facc[i][0], ap[i], bp0.x);
                fma2(facc[i][1], ap[i], bp0.y);
                fma2(facc[i][2], ap[i], bp1.x);
                fma2(facc[i][3], ap[i], bp1.y);
            }
        }
        __syncthreads();
    }

    // epilogue: scale + CT gather + store
    int cats[TN];
    #pragma unroll
    for (int j = 0; j < TN; j++) {
        int c = col0 + tx * TN + j;
        cats[j] = (c < M_ITEMS) ? __ldg(&item_cat[c]) : 0;
    }
    const float scale = 0.0625f;     // 0.25 (user layer-mean) * 0.25 (item layer-mean)
    #pragma unroll
    for (int i = 0; i < TM; i++) {
        int r = row0 + ty * TM + i;            // always < 1024
        float ct[TN];
        #pragma unroll
        for (int j = 0; j < TN; j++) ct[j] = __ldg(&CT[(size_t)cats[j] * BATCH + r]);
        #pragma unroll
        for (int j = 0; j < TN / 2; j += 2) {
            int c = col0 + tx * TN + j * 2;
            if (c < M_ITEMS) {
                float2 v0 = unpack2(facc[i][j]);
                float2 v1 = unpack2(facc[i][j + 1]);
                float4 o = make_float4(scale * v0.x + ct[j * 2 + 0],
                                       scale * v0.y + ct[j * 2 + 1],
                                       scale * v1.x + ct[j * 2 + 2],
                                       scale * v1.y + ct[j * 2 + 3]);
                *(float4*)(C + (size_t)r * M_ITEMS + c) = o;
            }
        }
    }
}

// ---------------- launch ----------------
extern "C" void kernel_launch(void* const* d_in, const int* in_sizes, int n_in,
                              void* d_out, int out_size) {
    const float* user_emb  = (const float*)d_in[0];
    const float* item_emb  = (const float*)d_in[1];
    const float* cat_emb   = (const float*)d_in[2];
    const float* graph_vals= (const float*)d_in[3];
    const int*   graph_rows= (const int*)  d_in[4];
    const int*   graph_cols= (const int*)  d_in[5];
    const int*   uh3       = (const int*)  d_in[6];
    const int*   item_cat  = (const int*)  d_in[7];
    const int*   users     = (const int*)  d_in[8];
    const float* thetas    = (const float*)d_in[9];
    float* out = (float*)d_out;

    __half *d_h0, *d_h1;
    float *d_acc, *d_Vc, *d_CT;
    int2* d_edge; int *d_cnt, *d_rowstart, *d_cursor, *d_blocksums;
    unsigned char* d_need;
    cudaGetSymbolAddress((void**)&d_h0,       g_h0);
    cudaGetSymbolAddress((void**)&d_h1,       g_h1);
    cudaGetSymbolAddress((void**)&d_acc,      g_acc);
    cudaGetSymbolAddress((void**)&d_Vc,       g_Vc);
    cudaGetSymbolAddress((void**)&d_CT,       g_CT);
    cudaGetSymbolAddress((void**)&d_edge,     g_edge);
    cudaGetSymbolAddress((void**)&d_cnt,      g_cnt);
    cudaGetSymbolAddress((void**)&d_rowstart, g_rowstart);
    cudaGetSymbolAddress((void**)&d_cursor,   g_cursor);
    cudaGetSymbolAddress((void**)&d_blocksums,g_blocksums);
    cudaGetSymbolAddress((void**)&d_need,     g_need);

    // 1: init (h0 + zero cnt/need)
    {
        int total = N_NODES * (LATENT / 4);
        k_init<<<(total + 255) / 256, 256>>>(user_emb, item_emb, d_h0, d_cnt, d_need);
    }
    // 2-5: CSR build
    k_count<<<(NNZ / 4 + 255) / 256, 256>>>(graph_rows, d_cnt);
    k_scan_blocks<<<NBLK, 256>>>(d_cnt, d_rowstart, d_blocksums);
    k_add_offsets<<<NBLK * 4, 256>>>(d_rowstart, d_blocksums, d_cursor);
    k_fill<<<(NNZ / 4 + 255) / 256, 256>>>(graph_vals, graph_rows, graph_cols, d_cursor, d_edge);

    // 6-9: LightGCN layers
    {
        int th = N_NODES * 8;
        int blocks = (th + 255) / 256;
        k_gather<<<blocks, 256>>>(d_edge, d_rowstart, d_cnt, d_h0, d_h1, d_acc, d_need,
                                  user_emb, item_emb, 1);   // L1: acc = emb + s
        k_gather<<<blocks, 256>>>(d_edge, d_rowstart, d_cnt, d_h1, d_h0, d_acc, d_need,
                                  user_emb, item_emb, 0);   // L2: acc += s
        k_setflags<<<(BATCH + 255) / 256, 256>>>(users, d_need);
        k_gather<<<blocks, 256>>>(d_edge, d_rowstart, d_cnt, d_h0, d_h1, d_acc, d_need,
                                  user_emb, item_emb, 2);   // L3: selective
    }

    // 10-11: clock path
    k_vclock<<<BATCH, 64>>>(cat_emb, uh3, users, thetas, d_Vc);
    {
        dim3 grid(BATCH / 256, (N_CATS + CT_CATS - 1) / CT_CATS);
        k_ct<<<grid, 256>>>(cat_emb, d_Vc, d_CT);
    }

    // 12: fused GEMM (K=64) + CT gather epilogue
    {
        dim3 grid(M_PAD / BN, BATCH / BM);
        k_gemm<<<grid, 256>>>(d_acc, users, item_cat, d_CT, out);
    }
}